// round 4
// baseline (speedup 1.0000x reference)
#include <cuda_runtime.h>

// ---------------- problem dims ----------------
#define NWIN   4096
#define NGT    49
#define NTOK   50
#define CDIM   128
#define HEADS  4
#define HD     32
#define BIMG   64
#define NTPAT  3136
#define WQ_SCALE 0.17677669529663687f   // 32^-0.5

// ---------------- device scratch ----------------
__device__ float g_Q [200704u * 128u];
__device__ float g_Kw[204800u * 128u];
__device__ float g_Vw[204800u * 128u];
__device__ float g_Kg[200704u * 128u];
__device__ float g_Vg[200704u * 128u];
__device__ float g_bias[HEADS * NGT * NTOK];

__device__ __forceinline__ unsigned tfu(float f) {
    unsigned r;
    asm("cvt.rna.tf32.f32 %0, %1;" : "=r"(r) : "f"(f));
    return r;
}
__device__ __forceinline__ float tfv(float f) { return __uint_as_float(tfu(f)); }

__device__ __forceinline__ void mma_tf32(float* c,
                                         const unsigned* a,
                                         unsigned b0, unsigned b1)
{
    asm volatile("mma.sync.aligned.m16n8k8.row.col.f32.tf32.tf32.f32 "
                 "{%0,%1,%2,%3}, {%4,%5,%6,%7}, {%8,%9}, {%0,%1,%2,%3};"
                 : "+f"(c[0]), "+f"(c[1]), "+f"(c[2]), "+f"(c[3])
                 : "r"(a[0]), "r"(a[1]), "r"(a[2]), "r"(a[3]), "r"(b0), "r"(b1));
}

// =====================================================================
// 3xTF32 projection GEMM: C[M, 128|256] = (A[M,128] @ W[128,N] + b)*alpha
// Block 128x128; B panel (full K) hi+lo resident; A hi+lo double-buffered.
// 8 warps = 2(m) x 4(n), warp tile 64x32.
// =====================================================================
#define SB_STR 136
#define SA_STR 36
#define SB_SZ  (128 * SB_STR)    // 17408 floats
#define SA_SZ  (128 * SA_STR)    // 4608 floats
#define GEMM_SMEM ((2 * SB_SZ + 4 * SA_SZ) * 4)   // 212992 bytes

template<int GATHER, int DST>
__global__ void __launch_bounds__(256)
mma_gemm(const float* __restrict__ A, const float* __restrict__ Aavg,
         const float* __restrict__ W, const float* __restrict__ bias,
         int N, float alpha)
{
    extern __shared__ float smem[];
    float* sBh = smem;
    float* sBl = smem + SB_SZ;
    float* sA  = smem + 2 * SB_SZ;   // [buf][hi/lo][128][36]; buf stride 2*SA_SZ

    const int tid  = threadIdx.x;
    const int lane = tid & 31;
    const int warp = tid >> 5;
    const int wm   = warp >> 2;
    const int wn   = warp & 3;
    const int g4   = lane >> 2;
    const int t4   = lane & 3;
    const int nblk = blockIdx.x * 128;
    const int by   = blockIdx.y;

    const int a_row  = tid >> 1;
    const int a_half = (tid & 1) * 16;
    const int m = by * 128 + a_row;
    const float* arow;
    if (GATHER) {
        int w  = m / NTOK;
        int rr = m - w * NTOK;
        arow = (rr < NGT) ? (A    + (size_t)(w * NGT + rr) * CDIM)
                          : (Aavg + (size_t)(w >> 6)       * CDIM);
    } else {
        arow = A + (size_t)m * CDIM;
    }

    // ---- B panel hi/lo ----
    #pragma unroll
    for (int i = 0; i < 16; i++) {
        int idx = tid + 256 * i;
        int kk  = idx >> 5;
        int n4  = (idx & 31) << 2;
        float4 v = *(const float4*)(W + (size_t)kk * N + nblk + n4);
        float4 hi, lo;
        hi.x = tfv(v.x); lo.x = tfv(v.x - hi.x);
        hi.y = tfv(v.y); lo.y = tfv(v.y - hi.y);
        hi.z = tfv(v.z); lo.z = tfv(v.z - hi.z);
        hi.w = tfv(v.w); lo.w = tfv(v.w - hi.w);
        *(float4*)&sBh[kk * SB_STR + n4] = hi;
        *(float4*)&sBl[kk * SB_STR + n4] = lo;
    }

    // ---- A prologue ----
    float4 areg[4];
    #pragma unroll
    for (int j = 0; j < 4; j++)
        areg[j] = *(const float4*)(arow + a_half + 4 * j);
    {
        float* dh = sA + a_row * SA_STR + a_half;
        float* dl = dh + SA_SZ;
        #pragma unroll
        for (int j = 0; j < 4; j++) {
            float4 hi, lo;
            hi.x = tfv(areg[j].x); lo.x = tfv(areg[j].x - hi.x);
            hi.y = tfv(areg[j].y); lo.y = tfv(areg[j].y - hi.y);
            hi.z = tfv(areg[j].z); lo.z = tfv(areg[j].z - hi.z);
            hi.w = tfv(areg[j].w); lo.w = tfv(areg[j].w - hi.w);
            *(float4*)(dh + 4 * j) = hi;
            *(float4*)(dl + 4 * j) = lo;
        }
    }
    __syncthreads();

    float acc[4][4][4];
    #pragma unroll
    for (int mf = 0; mf < 4; mf++)
        #pragma unroll
        for (int nf = 0; nf < 4; nf++)
            #pragma unroll
            for (int c = 0; c < 4; c++) acc[mf][nf][c] = 0.0f;

    const int a_m0 = wm * 64;
    const int b_n0 = wn * 32;

    for (int kt = 0; kt < 4; kt++) {
        if (kt < 3) {
            #pragma unroll
            for (int j = 0; j < 4; j++)
                areg[j] = *(const float4*)(arow + (kt + 1) * 32 + a_half + 4 * j);
        }
        const float* AsH = sA + (kt & 1) * (2 * SA_SZ);
        const float* AsL = AsH + SA_SZ;
        #pragma unroll
        for (int ks = 0; ks < 4; ks++) {
            const int k0 = ks * 8;
            unsigned ah[4][4], al[4][4];
            #pragma unroll
            for (int mf = 0; mf < 4; mf++) {
                const float* ph = AsH + (a_m0 + mf * 16 + g4) * SA_STR + k0 + t4;
                const float* pl = AsL + (a_m0 + mf * 16 + g4) * SA_STR + k0 + t4;
                ah[mf][0] = __float_as_uint(ph[0]);
                ah[mf][1] = __float_as_uint(ph[8 * SA_STR]);
                ah[mf][2] = __float_as_uint(ph[4]);
                ah[mf][3] = __float_as_uint(ph[8 * SA_STR + 4]);
                al[mf][0] = __float_as_uint(pl[0]);
                al[mf][1] = __float_as_uint(pl[8 * SA_STR]);
                al[mf][2] = __float_as_uint(pl[4]);
                al[mf][3] = __float_as_uint(pl[8 * SA_STR + 4]);
            }
            #pragma unroll
            for (int nf = 0; nf < 4; nf++) {
                const float* bh = sBh + (kt * 32 + k0 + t4) * SB_STR + b_n0 + nf * 8 + g4;
                const float* bl = sBl + (kt * 32 + k0 + t4) * SB_STR + b_n0 + nf * 8 + g4;
                unsigned bh0 = __float_as_uint(bh[0]);
                unsigned bh1 = __float_as_uint(bh[4 * SB_STR]);
                unsigned bl0 = __float_as_uint(bl[0]);
                unsigned bl1 = __float_as_uint(bl[4 * SB_STR]);
                #pragma unroll
                for (int mf = 0; mf < 4; mf++) {
                    mma_tf32(acc[mf][nf], ah[mf], bl0, bl1);
                    mma_tf32(acc[mf][nf], al[mf], bh0, bh1);
                    mma_tf32(acc[mf][nf], ah[mf], bh0, bh1);
                }
            }
        }
        if (kt < 3) {
            __syncthreads();
            float* dh = sA + ((kt + 1) & 1) * (2 * SA_SZ) + a_row * SA_STR + a_half;
            float* dl = dh + SA_SZ;
            #pragma unroll
            for (int j = 0; j < 4; j++) {
                float4 hi, lo;
                hi.x = tfv(areg[j].x); lo.x = tfv(areg[j].x - hi.x);
                hi.y = tfv(areg[j].y); lo.y = tfv(areg[j].y - hi.y);
                hi.z = tfv(areg[j].z); lo.z = tfv(areg[j].z - hi.z);
                hi.w = tfv(areg[j].w); lo.w = tfv(areg[j].w - hi.w);
                *(float4*)(dh + 4 * j) = hi;
                *(float4*)(dl + 4 * j) = lo;
            }
            __syncthreads();
        }
    }

    float* Cout;
    if (DST == 0)       Cout = g_Q;
    else if (DST == 1)  Cout = (blockIdx.x == 0) ? g_Kw : g_Vw;
    else                Cout = (blockIdx.x == 0) ? g_Kg : g_Vg;

    #pragma unroll
    for (int mf = 0; mf < 4; mf++) {
        int row0 = by * 128 + a_m0 + mf * 16 + g4;
        #pragma unroll
        for (int nf = 0; nf < 4; nf++) {
            int ncol = b_n0 + nf * 8 + 2 * t4;
            float bb0 = bias[nblk + ncol];
            float bb1 = bias[nblk + ncol + 1];
            float2 v0, v1;
            v0.x = (acc[mf][nf][0] + bb0) * alpha;
            v0.y = (acc[mf][nf][1] + bb1) * alpha;
            v1.x = (acc[mf][nf][2] + bb0) * alpha;
            v1.y = (acc[mf][nf][3] + bb1) * alpha;
            *(float2*)(Cout + (size_t)row0 * 128 + ncol)       = v0;
            *(float2*)(Cout + (size_t)(row0 + 8) * 128 + ncol) = v1;
        }
    }
}

// ---------------- bias gather ----------------
__global__ void bias_build_kernel(const float* __restrict__ table,
                                  const int* __restrict__ ridx)
{
    int idx = blockIdx.x * 256 + threadIdx.x;
    if (idx < HEADS * NGT * NTOK) {
        int h  = idx / (NGT * NTOK);
        int ij = idx - h * (NGT * NTOK);
        g_bias[idx] = table[ridx[ij] * HEADS + h];
    }
}

// =====================================================================
// Window attention with TF32 MMA. One block = one window, 4 warps = heads.
// S(49x50) = Q K^T via mma; in-register softmax; O = P V via mma with
// P hi/lo split (shuffle-converted acc->A fragments, no smem round-trip).
// =====================================================================
#define WQ_STR 132
#define WK_STR 132
#define WV_STR 136
#define S_SK   (64 * WQ_STR)             // 8448
#define S_SV   (S_SK + 56 * WK_STR)      // 15840
#define WIN_SMEM ((S_SV + 56 * WV_STR) * 4)   // 93824 bytes

__global__ void __launch_bounds__(128)
win_attn_mma(const float* __restrict__ mask, float* __restrict__ out)
{
    extern __shared__ float sm[];
    float* sq = sm;
    float* sk = sm + S_SK;
    float* sv = sm + S_SV;

    const int w    = blockIdx.x;
    const int tid  = threadIdx.x;
    const int h    = tid >> 5;           // warp = head
    const int lane = tid & 31;
    const int g4   = lane >> 2;
    const int t4   = lane & 3;

    // zero pad rows (Q rows 49..63, K/V rows 50..55)
    for (int i = tid; i < 15 * WQ_STR; i += 128) sq[49 * WQ_STR + i] = 0.0f;
    for (int i = tid; i < 6 * WK_STR; i += 128)  sk[50 * WK_STR + i] = 0.0f;
    for (int i = tid; i < 6 * WV_STR; i += 128)  sv[50 * WV_STR + i] = 0.0f;

    // fill Q (tf32-rounded), 49 rows x 128 cols
    for (int idx = tid; idx < 49 * 32; idx += 128) {
        int r = idx >> 5, c4 = (idx & 31) << 2;
        float4 v = *(const float4*)(g_Q + (size_t)(w * NGT + r) * CDIM + c4);
        v.x = tfv(v.x); v.y = tfv(v.y); v.z = tfv(v.z); v.w = tfv(v.w);
        *(float4*)&sq[r * WQ_STR + c4] = v;
    }
    // fill K, V (tf32-rounded), 50 rows x 128 cols
    for (int idx = tid; idx < 50 * 32; idx += 128) {
        int r = idx >> 5, c4 = (idx & 31) << 2;
        size_t off = (size_t)(w * NTOK + r) * CDIM + c4;
        float4 kk = *(const float4*)(g_Kw + off);
        float4 vv = *(const float4*)(g_Vw + off);
        kk.x = tfv(kk.x); kk.y = tfv(kk.y); kk.z = tfv(kk.z); kk.w = tfv(kk.w);
        vv.x = tfv(vv.x); vv.y = tfv(vv.y); vv.z = tfv(vv.z); vv.w = tfv(vv.w);
        *(float4*)&sk[r * WK_STR + c4] = kk;
        *(float4*)&sv[r * WV_STR + c4] = vv;
    }
    __syncthreads();

    // ---- S = Q K^T  (M=64 pad, N=56 pad, K=32) ----
    float sacc[4][7][4];
    #pragma unroll
    for (int mf = 0; mf < 4; mf++)
        #pragma unroll
        for (int nf = 0; nf < 7; nf++)
            #pragma unroll
            for (int c = 0; c < 4; c++) sacc[mf][nf][c] = 0.0f;

    #pragma unroll
    for (int ks = 0; ks < 4; ks++) {
        unsigned a[4][4];
        #pragma unroll
        for (int mf = 0; mf < 4; mf++) {
            const float* ap = sq + (16 * mf + g4) * WQ_STR + h * HD + 8 * ks + t4;
            a[mf][0] = __float_as_uint(ap[0]);
            a[mf][1] = __float_as_uint(ap[8 * WQ_STR]);
            a[mf][2] = __float_as_uint(ap[4]);
            a[mf][3] = __float_as_uint(ap[8 * WQ_STR + 4]);
        }
        #pragma unroll
        for (int nf = 0; nf < 7; nf++) {
            const float* bp = sk + (8 * nf + g4) * WK_STR + h * HD + 8 * ks + t4;
            unsigned b0 = __float_as_uint(bp[0]);
            unsigned b1 = __float_as_uint(bp[4]);
            #pragma unroll
            for (int mf = 0; mf < 4; mf++)
                mma_tf32(sacc[mf][nf], a[mf], b0, b1);
        }
    }

    // ---- bias + mask + softmax (values kept in sacc, become P) ----
    const float* bptr = g_bias + h * (NGT * NTOK);
    const float* mptr = mask + (size_t)(w & 63) * (NGT * NTOK);
    float rs0[4], rs1[4];

    #pragma unroll
    for (int mf = 0; mf < 4; mf++) {
        const int i0 = 16 * mf + g4;
        const int i1 = i0 + 8;
        float m0 = -1e30f, m1 = -1e30f;
        #pragma unroll
        for (int nf = 0; nf < 7; nf++) {
            const int j0 = 8 * nf + 2 * t4;
            const int j1 = j0 + 1;
            float s0 = (i0 < NGT && j0 < NTOK) ? sacc[mf][nf][0] + bptr[i0 * 50 + j0] + mptr[i0 * 50 + j0] : -1e30f;
            float s1 = (i0 < NGT && j1 < NTOK) ? sacc[mf][nf][1] + bptr[i0 * 50 + j1] + mptr[i0 * 50 + j1] : -1e30f;
            float s2 = (i1 < NGT && j0 < NTOK) ? sacc[mf][nf][2] + bptr[i1 * 50 + j0] + mptr[i1 * 50 + j0] : -1e30f;
            float s3 = (i1 < NGT && j1 < NTOK) ? sacc[mf][nf][3] + bptr[i1 * 50 + j1] + mptr[i1 * 50 + j1] : -1e30f;
            sacc[mf][nf][0] = s0; sacc[mf][nf][1] = s1;
            sacc[mf][nf][2] = s2; sacc[mf][nf][3] = s3;
            m0 = fmaxf(m0, fmaxf(s0, s1));
            m1 = fmaxf(m1, fmaxf(s2, s3));
        }
        m0 = fmaxf(m0, __shfl_xor_sync(0xffffffffu, m0, 1));
        m0 = fmaxf(m0, __shfl_xor_sync(0xffffffffu, m0, 2));
        m1 = fmaxf(m1, __shfl_xor_sync(0xffffffffu, m1, 1));
        m1 = fmaxf(m1, __shfl_xor_sync(0xffffffffu, m1, 2));
        float r0 = 0.0f, r1 = 0.0f;
        #pragma unroll
        for (int nf = 0; nf < 7; nf++) {
            float p0 = __expf(sacc[mf][nf][0] - m0);
            float p1 = __expf(sacc[mf][nf][1] - m0);
            float p2 = __expf(sacc[mf][nf][2] - m1);
            float p3 = __expf(sacc[mf][nf][3] - m1);
            sacc[mf][nf][0] = p0; sacc[mf][nf][1] = p1;
            sacc[mf][nf][2] = p2; sacc[mf][nf][3] = p3;
            r0 += p0 + p1;
            r1 += p2 + p3;
        }
        r0 += __shfl_xor_sync(0xffffffffu, r0, 1);
        r0 += __shfl_xor_sync(0xffffffffu, r0, 2);
        r1 += __shfl_xor_sync(0xffffffffu, r1, 1);
        r1 += __shfl_xor_sync(0xffffffffu, r1, 2);
        rs0[mf] = r0; rs1[mf] = r1;
    }

    // ---- O = P V  (K=56 pad, N=32), P hi/lo 2-pass ----
    float oacc[4][4][4];
    #pragma unroll
    for (int mf = 0; mf < 4; mf++)
        #pragma unroll
        for (int nf = 0; nf < 4; nf++)
            #pragma unroll
            for (int c = 0; c < 4; c++) oacc[mf][nf][c] = 0.0f;

    const int sl0 = (lane & ~3) | (t4 >> 1);
    const int sl2 = sl0 + 2;
    const bool odd = (t4 & 1) != 0;

    #pragma unroll
    for (int ks = 0; ks < 7; ks++) {
        unsigned Ah[4][4], Al[4][4];
        #pragma unroll
        for (int mf = 0; mf < 4; mf++) {
            float q0 = __shfl_sync(0xffffffffu, sacc[mf][ks][0], sl0);
            float q1 = __shfl_sync(0xffffffffu, sacc[mf][ks][1], sl0);
            float q2 = __shfl_sync(0xffffffffu, sacc[mf][ks][2], sl0);
            float q3 = __shfl_sync(0xffffffffu, sacc[mf][ks][3], sl0);
            float r0 = __shfl_sync(0xffffffffu, sacc[mf][ks][0], sl2);
            float r1 = __shfl_sync(0xffffffffu, sacc[mf][ks][1], sl2);
            float r2 = __shfl_sync(0xffffffffu, sacc[mf][ks][2], sl2);
            float r3 = __shfl_sync(0xffffffffu, sacc[mf][ks][3], sl2);
            float f0 = odd ? q1 : q0;       // (row g4,   col 8ks+t4)
            float f1 = odd ? q3 : q2;       // (row g4+8, col 8ks+t4)
            float f2 = odd ? r1 : r0;       // (row g4,   col 8ks+t4+4)
            float f3 = odd ? r3 : r2;       // (row g4+8, col 8ks+t4+4)
            Ah[mf][0] = tfu(f0); Al[mf][0] = tfu(f0 - __uint_as_float(Ah[mf][0]));
            Ah[mf][1] = tfu(f1); Al[mf][1] = tfu(f1 - __uint_as_float(Ah[mf][1]));
            Ah[mf][2] = tfu(f2); Al[mf][2] = tfu(f2 - __uint_as_float(Ah[mf][2]));
            Ah[mf][3] = tfu(f3); Al[mf][3] = tfu(f3 - __uint_as_float(Ah[mf][3]));
        }
        #pragma unroll
        for (int nf = 0; nf < 4; nf++) {
            const float* bp = sv + (8 * ks + t4) * WV_STR + h * HD + 8 * nf + g4;
            unsigned b0 = __float_as_uint(bp[0]);
            unsigned b1 = __float_as_uint(bp[4 * WV_STR]);
            #pragma unroll
            for (int mf = 0; mf < 4; mf++) {
                mma_tf32(oacc[mf][nf], Al[mf], b0, b1);
                mma_tf32(oacc[mf][nf], Ah[mf], b0, b1);
            }
        }
    }

    // ---- normalize + store ----
    #pragma unroll
    for (int mf = 0; mf < 4; mf++) {
        const int i0 = 16 * mf + g4;
        const int i1 = i0 + 8;
        const float inv0 = 1.0f / rs0[mf];
        const float inv1 = 1.0f / rs1[mf];
        #pragma unroll
        for (int nf = 0; nf < 4; nf++) {
            const int col = h * HD + 8 * nf + 2 * t4;
            if (i0 < NGT) {
                float2 v; v.x = oacc[mf][nf][0] * inv0; v.y = oacc[mf][nf][1] * inv0;
                *(float2*)(out + (size_t)(w * NGT + i0) * CDIM + col) = v;
            }
            if (i1 < NGT) {
                float2 v; v.x = oacc[mf][nf][2] * inv1; v.y = oacc[mf][nf][3] * inv1;
                *(float2*)(out + (size_t)(w * NGT + i1) * CDIM + col) = v;
            }
        }
    }
}

// ---------------- global-token attention (fp32, MLP-unrolled) ----------
__global__ void __launch_bounds__(512)
glob_attn_kernel(const float* __restrict__ xavg, const float* __restrict__ Wq,
                 const float* __restrict__ bq, float* __restrict__ out)
{
    const int b = blockIdx.x;
    const int h = blockIdx.y;
    const int tid  = threadIdx.x;
    const int warp = tid >> 5;
    const int lane = tid & 31;

    __shared__ float qa[32];
    __shared__ float logits[NTPAT];
    __shared__ float red[512];
    __shared__ float ored[16][33];

    if (tid < 32) {
        float acc = bq[h * HD + tid];
        const float* xr = xavg + (size_t)b * CDIM;
        for (int c = 0; c < CDIM; c++)
            acc += xr[c] * Wq[c * CDIM + h * HD + tid];
        qa[tid] = acc;
    }
    __syncthreads();

    const float* Kb = g_Kg + (size_t)b * NTPAT * CDIM + h * HD;
    const float  qv = qa[lane];
    for (int m0 = warp * 4; m0 < NTPAT; m0 += 64) {
        float p0 = qv * Kb[(size_t)(m0 + 0) * CDIM + lane];
        float p1 = qv * Kb[(size_t)(m0 + 1) * CDIM + lane];
        float p2 = qv * Kb[(size_t)(m0 + 2) * CDIM + lane];
        float p3 = qv * Kb[(size_t)(m0 + 3) * CDIM + lane];
        #pragma unroll
        for (int o = 16; o; o >>= 1) {
            p0 += __shfl_down_sync(0xffffffffu, p0, o);
            p1 += __shfl_down_sync(0xffffffffu, p1, o);
            p2 += __shfl_down_sync(0xffffffffu, p2, o);
            p3 += __shfl_down_sync(0xffffffffu, p3, o);
        }
        if (lane == 0) {
            logits[m0 + 0] = p0; logits[m0 + 1] = p1;
            logits[m0 + 2] = p2; logits[m0 + 3] = p3;
        }
    }
    __syncthreads();

    float mx = -1e30f;
    for (int m = tid; m < NTPAT; m += 512) mx = fmaxf(mx, logits[m]);
    red[tid] = mx; __syncthreads();
    for (int s = 256; s; s >>= 1) { if (tid < s) red[tid] = fmaxf(red[tid], red[tid + s]); __syncthreads(); }
    mx = red[0]; __syncthreads();

    float sum = 0.0f;
    for (int m = tid; m < NTPAT; m += 512) {
        float e = expf(logits[m] - mx);
        logits[m] = e;
        sum += e;
    }
    red[tid] = sum; __syncthreads();
    for (int s = 256; s; s >>= 1) { if (tid < s) red[tid] += red[tid + s]; __syncthreads(); }
    sum = red[0];
    __syncthreads();

    const float* Vb = g_Vg + (size_t)b * NTPAT * CDIM + h * HD;
    float acc = 0.0f;
    for (int m0 = warp * 4; m0 < NTPAT; m0 += 64) {
        float v0 = Vb[(size_t)(m0 + 0) * CDIM + lane];
        float v1 = Vb[(size_t)(m0 + 1) * CDIM + lane];
        float v2 = Vb[(size_t)(m0 + 2) * CDIM + lane];
        float v3 = Vb[(size_t)(m0 + 3) * CDIM + lane];
        acc += logits[m0] * v0 + logits[m0 + 1] * v1
             + logits[m0 + 2] * v2 + logits[m0 + 3] * v3;
    }
    ored[warp][lane] = acc;
    __syncthreads();
    if (tid < 32) {
        float a = 0.0f;
        #pragma unroll
        for (int p = 0; p < 16; p++) a += ored[p][tid];
        out[(size_t)b * CDIM + h * HD + tid] = a / sum;
    }
}

// ---------------- launch ----------------
extern "C" void kernel_launch(void* const* d_in, const int* in_sizes, int n_in,
                              void* d_out, int out_size)
{
    const float* x      = (const float*)d_in[0];
    const float* xtotal = (const float*)d_in[1];
    const float* xavg   = (const float*)d_in[2];
    const float* mask   = (const float*)d_in[3];
    const float* Wq     = (const float*)d_in[4];
    const float* bq     = (const float*)d_in[5];
    const float* Wkv    = (const float*)d_in[6];
    const float* bkv    = (const float*)d_in[7];
    const float* btab   = (const float*)d_in[8];
    const int*   ridx   = (const int*)d_in[9];

    float* out     = (float*)d_out;
    float* out_avg = out + (size_t)200704u * 128u;

    cudaFuncSetAttribute(mma_gemm<0, 0>, cudaFuncAttributeMaxDynamicSharedMemorySize, GEMM_SMEM);
    cudaFuncSetAttribute(mma_gemm<1, 1>, cudaFuncAttributeMaxDynamicSharedMemorySize, GEMM_SMEM);
    cudaFuncSetAttribute(mma_gemm<0, 2>, cudaFuncAttributeMaxDynamicSharedMemorySize, GEMM_SMEM);
    cudaFuncSetAttribute(win_attn_mma, cudaFuncAttributeMaxDynamicSharedMemorySize, WIN_SMEM);

    bias_build_kernel<<<(HEADS * NGT * NTOK + 255) / 256, 256>>>(btab, ridx);

    mma_gemm<0, 0><<<dim3(1, 1568), 256, GEMM_SMEM>>>(x, nullptr, Wq, bq, 128, WQ_SCALE);
    mma_gemm<1, 1><<<dim3(2, 1600), 256, GEMM_SMEM>>>(x, xavg, Wkv, bkv, 256, 1.0f);
    mma_gemm<0, 2><<<dim3(2, 1568), 256, GEMM_SMEM>>>(xtotal, nullptr, Wkv, bkv, 256, 1.0f);

    win_attn_mma<<<NWIN, 128, WIN_SMEM>>>(mask, out);
    glob_attn_kernel<<<dim3(BIMG, HEADS), 512>>>(xavg, Wq, bq, out_avg);
}

// round 5
// speedup vs baseline: 1.3253x; 1.3253x over previous
#include <cuda_runtime.h>
#include <cuda_bf16.h>

// ---------------- problem dims ----------------
#define NWIN   4096
#define NGT    49
#define NTOK   50
#define CDIM   128
#define HEADS  4
#define HD     32
#define BIMG   64
#define NTPAT  3136
#define WQ_SCALE 0.17677669529663687f   // 32^-0.5

// ---------------- device scratch ----------------
__device__ float g_Q [200704u * 128u];
__device__ float g_Kw[204800u * 128u];
__device__ float g_Vw[204800u * 128u];
__device__ float g_Kg[200704u * 128u];
__device__ float g_Vg[200704u * 128u];
__device__ float g_bias[HEADS * NGT * NTOK];

__device__ __forceinline__ unsigned tfu(float f) {
    unsigned r;
    asm("cvt.rna.tf32.f32 %0, %1;" : "=r"(r) : "f"(f));
    return r;
}
__device__ __forceinline__ float tfv(float f) { return __uint_as_float(tfu(f)); }

__device__ __forceinline__ void mma_tf32(float* c, const unsigned* a,
                                         unsigned b0, unsigned b1)
{
    asm volatile("mma.sync.aligned.m16n8k8.row.col.f32.tf32.tf32.f32 "
                 "{%0,%1,%2,%3}, {%4,%5,%6,%7}, {%8,%9}, {%0,%1,%2,%3};"
                 : "+f"(c[0]), "+f"(c[1]), "+f"(c[2]), "+f"(c[3])
                 : "r"(a[0]), "r"(a[1]), "r"(a[2]), "r"(a[3]), "r"(b0), "r"(b1));
}

__device__ __forceinline__ void mma_bf16(float* c, const unsigned* a,
                                         unsigned b0, unsigned b1)
{
    asm volatile("mma.sync.aligned.m16n8k16.row.col.f32.bf16.bf16.f32 "
                 "{%0,%1,%2,%3}, {%4,%5,%6,%7}, {%8,%9}, {%0,%1,%2,%3};"
                 : "+f"(c[0]), "+f"(c[1]), "+f"(c[2]), "+f"(c[3])
                 : "r"(a[0]), "r"(a[1]), "r"(a[2]), "r"(a[3]), "r"(b0), "r"(b1));
}

__device__ __forceinline__ unsigned pk2(__nv_bfloat16 a, __nv_bfloat16 b) {
    __nv_bfloat162 t(a, b);
    return *reinterpret_cast<unsigned*>(&t);
}

// =====================================================================
// Split-BF16 projection GEMM: C = (A[M,128] @ W[128,N] + b) * alpha
// x = hi(bf16) + lo(bf16); acc += ah*bl + al*bh + ah*bh  (m16n8k16)
// Block 128x128; B full-K panel resident hi/lo [n][k]; A double-buffered
// hi/lo k=32 slices [m][k]. 8 warps = 2(m) x 4(n); warp tile 64x32.
// =====================================================================
#define SBB_STR 136                       // bf16 units per B row (272B, 4-bank shift)
#define SAB_STR 40                        // bf16 units per A row (80B, 20-bank shift)
#define SBB_PL  (128 * SBB_STR)           // 17408 bf16 per B plane
#define SAB_PL  (128 * SAB_STR)           // 5120 bf16 per A plane (one buf)
#define GEMM_SMEM ((2 * SBB_PL + 4 * SAB_PL) * 2)   // 110592 bytes

template<int GATHER, int DST>
__global__ void __launch_bounds__(256, 2)
bf16_gemm(const float* __restrict__ A, const float* __restrict__ Aavg,
          const float* __restrict__ W, const float* __restrict__ bias,
          int N, float alpha)
{
    extern __shared__ __nv_bfloat16 sm[];
    __nv_bfloat16* sBh = sm;                        // [128 n][136 k]
    __nv_bfloat16* sBl = sm + SBB_PL;
    __nv_bfloat16* sA  = sm + 2 * SBB_PL;           // [buf][hi/lo][128][40]

    const int tid  = threadIdx.x;
    const int lane = tid & 31;
    const int warp = tid >> 5;
    const int wm   = warp >> 2;
    const int wn   = warp & 3;
    const int g4   = lane >> 2;
    const int t4   = lane & 3;
    const int nblk = blockIdx.x * 128;
    const int by   = blockIdx.y;

    // ---- A row pointer ----
    const int a_row  = tid >> 1;
    const int a_half = (tid & 1) * 16;
    const int m = by * 128 + a_row;
    const float* arow;
    if (GATHER) {
        int w  = m / NTOK;
        int rr = m - w * NTOK;
        arow = (rr < NGT) ? (A    + (size_t)(w * NGT + rr) * CDIM)
                          : (Aavg + (size_t)(w >> 6)       * CDIM);
    } else {
        arow = A + (size_t)m * CDIM;
    }

    // ---- B panel: column-wise coalesced read, [n][k] hi/lo store ----
    {
        const int nloc  = (warp & 3) * 32 + lane;   // 0..127
        const int kbase = (warp >> 2) * 64;         // 0 or 64
        const float* wp = W + nblk + nloc;
        #pragma unroll
        for (int kg = 0; kg < 16; kg++) {
            const int k = kbase + kg * 4;
            float v0 = wp[(size_t)(k + 0) * N];
            float v1 = wp[(size_t)(k + 1) * N];
            float v2 = wp[(size_t)(k + 2) * N];
            float v3 = wp[(size_t)(k + 3) * N];
            __nv_bfloat16 h0 = __float2bfloat16(v0);
            __nv_bfloat16 h1 = __float2bfloat16(v1);
            __nv_bfloat16 h2 = __float2bfloat16(v2);
            __nv_bfloat16 h3 = __float2bfloat16(v3);
            __nv_bfloat16 l0 = __float2bfloat16(v0 - __bfloat162float(h0));
            __nv_bfloat16 l1 = __float2bfloat16(v1 - __bfloat162float(h1));
            __nv_bfloat16 l2 = __float2bfloat16(v2 - __bfloat162float(h2));
            __nv_bfloat16 l3 = __float2bfloat16(v3 - __bfloat162float(h3));
            *(uint2*)(sBh + nloc * SBB_STR + k) = make_uint2(pk2(h0, h1), pk2(h2, h3));
            *(uint2*)(sBl + nloc * SBB_STR + k) = make_uint2(pk2(l0, l1), pk2(l2, l3));
        }
    }

    // ---- A prologue (kt=0) ----
    float4 areg[4];
    #pragma unroll
    for (int j = 0; j < 4; j++)
        areg[j] = *(const float4*)(arow + a_half + 4 * j);
    {
        __nv_bfloat16* dh = sA + a_row * SAB_STR + a_half;
        __nv_bfloat16* dl = dh + SAB_PL;
        #pragma unroll
        for (int j = 0; j < 4; j++) {
            __nv_bfloat16 h0 = __float2bfloat16(areg[j].x);
            __nv_bfloat16 h1 = __float2bfloat16(areg[j].y);
            __nv_bfloat16 h2 = __float2bfloat16(areg[j].z);
            __nv_bfloat16 h3 = __float2bfloat16(areg[j].w);
            __nv_bfloat16 l0 = __float2bfloat16(areg[j].x - __bfloat162float(h0));
            __nv_bfloat16 l1 = __float2bfloat16(areg[j].y - __bfloat162float(h1));
            __nv_bfloat16 l2 = __float2bfloat16(areg[j].z - __bfloat162float(h2));
            __nv_bfloat16 l3 = __float2bfloat16(areg[j].w - __bfloat162float(h3));
            *(uint2*)(dh + 4 * j) = make_uint2(pk2(h0, h1), pk2(h2, h3));
            *(uint2*)(dl + 4 * j) = make_uint2(pk2(l0, l1), pk2(l2, l3));
        }
    }
    __syncthreads();

    float acc[4][4][4];
    #pragma unroll
    for (int mf = 0; mf < 4; mf++)
        #pragma unroll
        for (int nf = 0; nf < 4; nf++)
            #pragma unroll
            for (int c = 0; c < 4; c++) acc[mf][nf][c] = 0.0f;

    const int a_m0 = wm * 64;
    const int b_n0 = wn * 32;

    for (int kt = 0; kt < 4; kt++) {
        if (kt < 3) {
            #pragma unroll
            for (int j = 0; j < 4; j++)
                areg[j] = *(const float4*)(arow + (kt + 1) * 32 + a_half + 4 * j);
        }
        const __nv_bfloat16* Ah = sA + (kt & 1) * (2 * SAB_PL);
        const __nv_bfloat16* Al = Ah + SAB_PL;

        #pragma unroll
        for (int st = 0; st < 2; st++) {
            const int kloc  = st * 16;
            const int kglob = kt * 32 + kloc;
            unsigned ah[4][4], al[4][4];
            #pragma unroll
            for (int mf = 0; mf < 4; mf++) {
                const __nv_bfloat16* ph = Ah + (a_m0 + mf * 16 + g4) * SAB_STR + kloc + 2 * t4;
                const __nv_bfloat16* pl = Al + (a_m0 + mf * 16 + g4) * SAB_STR + kloc + 2 * t4;
                ah[mf][0] = *(const unsigned*)(ph);
                ah[mf][1] = *(const unsigned*)(ph + 8 * SAB_STR);
                ah[mf][2] = *(const unsigned*)(ph + 8);
                ah[mf][3] = *(const unsigned*)(ph + 8 * SAB_STR + 8);
                al[mf][0] = *(const unsigned*)(pl);
                al[mf][1] = *(const unsigned*)(pl + 8 * SAB_STR);
                al[mf][2] = *(const unsigned*)(pl + 8);
                al[mf][3] = *(const unsigned*)(pl + 8 * SAB_STR + 8);
            }
            #pragma unroll
            for (int nf = 0; nf < 4; nf++) {
                const __nv_bfloat16* bh = sBh + (b_n0 + nf * 8 + g4) * SBB_STR + kglob + 2 * t4;
                const __nv_bfloat16* bl = sBl + (b_n0 + nf * 8 + g4) * SBB_STR + kglob + 2 * t4;
                unsigned bh0 = *(const unsigned*)(bh);
                unsigned bh1 = *(const unsigned*)(bh + 8);
                unsigned bl0 = *(const unsigned*)(bl);
                unsigned bl1 = *(const unsigned*)(bl + 8);
                #pragma unroll
                for (int mf = 0; mf < 4; mf++) {
                    mma_bf16(acc[mf][nf], ah[mf], bl0, bl1);
                    mma_bf16(acc[mf][nf], al[mf], bh0, bh1);
                    mma_bf16(acc[mf][nf], ah[mf], bh0, bh1);
                }
            }
        }

        if (kt < 3) {
            __syncthreads();
            __nv_bfloat16* dh = sA + ((kt + 1) & 1) * (2 * SAB_PL) + a_row * SAB_STR + a_half;
            __nv_bfloat16* dl = dh + SAB_PL;
            #pragma unroll
            for (int j = 0; j < 4; j++) {
                __nv_bfloat16 h0 = __float2bfloat16(areg[j].x);
                __nv_bfloat16 h1 = __float2bfloat16(areg[j].y);
                __nv_bfloat16 h2 = __float2bfloat16(areg[j].z);
                __nv_bfloat16 h3 = __float2bfloat16(areg[j].w);
                __nv_bfloat16 l0 = __float2bfloat16(areg[j].x - __bfloat162float(h0));
                __nv_bfloat16 l1 = __float2bfloat16(areg[j].y - __bfloat162float(h1));
                __nv_bfloat16 l2 = __float2bfloat16(areg[j].z - __bfloat162float(h2));
                __nv_bfloat16 l3 = __float2bfloat16(areg[j].w - __bfloat162float(h3));
                *(uint2*)(dh + 4 * j) = make_uint2(pk2(h0, h1), pk2(h2, h3));
                *(uint2*)(dl + 4 * j) = make_uint2(pk2(l0, l1), pk2(l2, l3));
            }
            __syncthreads();
        }
    }

    float* Cout;
    if (DST == 0)       Cout = g_Q;
    else if (DST == 1)  Cout = (blockIdx.x == 0) ? g_Kw : g_Vw;
    else                Cout = (blockIdx.x == 0) ? g_Kg : g_Vg;

    #pragma unroll
    for (int mf = 0; mf < 4; mf++) {
        int row0 = by * 128 + a_m0 + mf * 16 + g4;
        #pragma unroll
        for (int nf = 0; nf < 4; nf++) {
            int ncol = b_n0 + nf * 8 + 2 * t4;
            float bb0 = bias[nblk + ncol];
            float bb1 = bias[nblk + ncol + 1];
            float2 v0, v1;
            v0.x = (acc[mf][nf][0] + bb0) * alpha;
            v0.y = (acc[mf][nf][1] + bb1) * alpha;
            v1.x = (acc[mf][nf][2] + bb0) * alpha;
            v1.y = (acc[mf][nf][3] + bb1) * alpha;
            *(float2*)(Cout + (size_t)row0 * 128 + ncol)       = v0;
            *(float2*)(Cout + (size_t)(row0 + 8) * 128 + ncol) = v1;
        }
    }
}

// ---------------- bias gather ----------------
__global__ void bias_build_kernel(const float* __restrict__ table,
                                  const int* __restrict__ ridx)
{
    int idx = blockIdx.x * 256 + threadIdx.x;
    if (idx < HEADS * NGT * NTOK) {
        int h  = idx / (NGT * NTOK);
        int ij = idx - h * (NGT * NTOK);
        g_bias[idx] = table[ridx[ij] * HEADS + h];
    }
}

// =====================================================================
// Window attention with TF32 MMA (unchanged from R3 — proven).
// =====================================================================
#define WQ_STR 132
#define WK_STR 132
#define WV_STR 136
#define S_SK   (64 * WQ_STR)
#define S_SV   (S_SK + 56 * WK_STR)
#define WIN_SMEM ((S_SV + 56 * WV_STR) * 4)

__global__ void __launch_bounds__(128)
win_attn_mma(const float* __restrict__ mask, float* __restrict__ out)
{
    extern __shared__ float smf[];
    float* sq = smf;
    float* sk = smf + S_SK;
    float* sv = smf + S_SV;

    const int w    = blockIdx.x;
    const int tid  = threadIdx.x;
    const int h    = tid >> 5;
    const int lane = tid & 31;
    const int g4   = lane >> 2;
    const int t4   = lane & 3;

    for (int i = tid; i < 15 * WQ_STR; i += 128) sq[49 * WQ_STR + i] = 0.0f;
    for (int i = tid; i < 6 * WK_STR; i += 128)  sk[50 * WK_STR + i] = 0.0f;
    for (int i = tid; i < 6 * WV_STR; i += 128)  sv[50 * WV_STR + i] = 0.0f;

    for (int idx = tid; idx < 49 * 32; idx += 128) {
        int r = idx >> 5, c4 = (idx & 31) << 2;
        float4 v = *(const float4*)(g_Q + (size_t)(w * NGT + r) * CDIM + c4);
        v.x = tfv(v.x); v.y = tfv(v.y); v.z = tfv(v.z); v.w = tfv(v.w);
        *(float4*)&sq[r * WQ_STR + c4] = v;
    }
    for (int idx = tid; idx < 50 * 32; idx += 128) {
        int r = idx >> 5, c4 = (idx & 31) << 2;
        size_t off = (size_t)(w * NTOK + r) * CDIM + c4;
        float4 kk = *(const float4*)(g_Kw + off);
        float4 vv = *(const float4*)(g_Vw + off);
        kk.x = tfv(kk.x); kk.y = tfv(kk.y); kk.z = tfv(kk.z); kk.w = tfv(kk.w);
        vv.x = tfv(vv.x); vv.y = tfv(vv.y); vv.z = tfv(vv.z); vv.w = tfv(vv.w);
        *(float4*)&sk[r * WK_STR + c4] = kk;
        *(float4*)&sv[r * WV_STR + c4] = vv;
    }
    __syncthreads();

    float sacc[4][7][4];
    #pragma unroll
    for (int mf = 0; mf < 4; mf++)
        #pragma unroll
        for (int nf = 0; nf < 7; nf++)
            #pragma unroll
            for (int c = 0; c < 4; c++) sacc[mf][nf][c] = 0.0f;

    #pragma unroll
    for (int ks = 0; ks < 4; ks++) {
        unsigned a[4][4];
        #pragma unroll
        for (int mf = 0; mf < 4; mf++) {
            const float* ap = sq + (16 * mf + g4) * WQ_STR + h * HD + 8 * ks + t4;
            a[mf][0] = __float_as_uint(ap[0]);
            a[mf][1] = __float_as_uint(ap[8 * WQ_STR]);
            a[mf][2] = __float_as_uint(ap[4]);
            a[mf][3] = __float_as_uint(ap[8 * WQ_STR + 4]);
        }
        #pragma unroll
        for (int nf = 0; nf < 7; nf++) {
            const float* bp = sk + (8 * nf + g4) * WK_STR + h * HD + 8 * ks + t4;
            unsigned b0 = __float_as_uint(bp[0]);
            unsigned b1 = __float_as_uint(bp[4]);
            #pragma unroll
            for (int mf = 0; mf < 4; mf++)
                mma_tf32(sacc[mf][nf], a[mf], b0, b1);
        }
    }

    const float* bptr = g_bias + h * (NGT * NTOK);
    const float* mptr = mask + (size_t)(w & 63) * (NGT * NTOK);
    float rs0[4], rs1[4];

    #pragma unroll
    for (int mf = 0; mf < 4; mf++) {
        const int i0 = 16 * mf + g4;
        const int i1 = i0 + 8;
        float m0 = -1e30f, m1 = -1e30f;
        #pragma unroll
        for (int nf = 0; nf < 7; nf++) {
            const int j0 = 8 * nf + 2 * t4;
            const int j1 = j0 + 1;
            float s0 = (i0 < NGT && j0 < NTOK) ? sacc[mf][nf][0] + bptr[i0 * 50 + j0] + mptr[i0 * 50 + j0] : -1e30f;
            float s1 = (i0 < NGT && j1 < NTOK) ? sacc[mf][nf][1] + bptr[i0 * 50 + j1] + mptr[i0 * 50 + j1] : -1e30f;
            float s2 = (i1 < NGT && j0 < NTOK) ? sacc[mf][nf][2] + bptr[i1 * 50 + j0] + mptr[i1 * 50 + j0] : -1e30f;
            float s3 = (i1 < NGT && j1 < NTOK) ? sacc[mf][nf][3] + bptr[i1 * 50 + j1] + mptr[i1 * 50 + j1] : -1e30f;
            sacc[mf][nf][0] = s0; sacc[mf][nf][1] = s1;
            sacc[mf][nf][2] = s2; sacc[mf][nf][3] = s3;
            m0 = fmaxf(m0, fmaxf(s0, s1));
            m1 = fmaxf(m1, fmaxf(s2, s3));
        }
        m0 = fmaxf(m0, __shfl_xor_sync(0xffffffffu, m0, 1));
        m0 = fmaxf(m0, __shfl_xor_sync(0xffffffffu, m0, 2));
        m1 = fmaxf(m1, __shfl_xor_sync(0xffffffffu, m1, 1));
        m1 = fmaxf(m1, __shfl_xor_sync(0xffffffffu, m1, 2));
        float r0 = 0.0f, r1 = 0.0f;
        #pragma unroll
        for (int nf = 0; nf < 7; nf++) {
            float p0 = __expf(sacc[mf][nf][0] - m0);
            float p1 = __expf(sacc[mf][nf][1] - m0);
            float p2 = __expf(sacc[mf][nf][2] - m1);
            float p3 = __expf(sacc[mf][nf][3] - m1);
            sacc[mf][nf][0] = p0; sacc[mf][nf][1] = p1;
            sacc[mf][nf][2] = p2; sacc[mf][nf][3] = p3;
            r0 += p0 + p1;
            r1 += p2 + p3;
        }
        r0 += __shfl_xor_sync(0xffffffffu, r0, 1);
        r0 += __shfl_xor_sync(0xffffffffu, r0, 2);
        r1 += __shfl_xor_sync(0xffffffffu, r1, 1);
        r1 += __shfl_xor_sync(0xffffffffu, r1, 2);
        rs0[mf] = r0; rs1[mf] = r1;
    }

    float oacc[4][4][4];
    #pragma unroll
    for (int mf = 0; mf < 4; mf++)
        #pragma unroll
        for (int nf = 0; nf < 4; nf++)
            #pragma unroll
            for (int c = 0; c < 4; c++) oacc[mf][nf][c] = 0.0f;

    const int sl0 = (lane & ~3) | (t4 >> 1);
    const int sl2 = sl0 + 2;
    const bool odd = (t4 & 1) != 0;

    #pragma unroll
    for (int ks = 0; ks < 7; ks++) {
        unsigned Ah[4][4], Al[4][4];
        #pragma unroll
        for (int mf = 0; mf < 4; mf++) {
            float q0 = __shfl_sync(0xffffffffu, sacc[mf][ks][0], sl0);
            float q1 = __shfl_sync(0xffffffffu, sacc[mf][ks][1], sl0);
            float q2 = __shfl_sync(0xffffffffu, sacc[mf][ks][2], sl0);
            float q3 = __shfl_sync(0xffffffffu, sacc[mf][ks][3], sl0);
            float r0 = __shfl_sync(0xffffffffu, sacc[mf][ks][0], sl2);
            float r1 = __shfl_sync(0xffffffffu, sacc[mf][ks][1], sl2);
            float r2 = __shfl_sync(0xffffffffu, sacc[mf][ks][2], sl2);
            float r3 = __shfl_sync(0xffffffffu, sacc[mf][ks][3], sl2);
            float f0 = odd ? q1 : q0;
            float f1 = odd ? q3 : q2;
            float f2 = odd ? r1 : r0;
            float f3 = odd ? r3 : r2;
            Ah[mf][0] = tfu(f0); Al[mf][0] = tfu(f0 - __uint_as_float(Ah[mf][0]));
            Ah[mf][1] = tfu(f1); Al[mf][1] = tfu(f1 - __uint_as_float(Ah[mf][1]));
            Ah[mf][2] = tfu(f2); Al[mf][2] = tfu(f2 - __uint_as_float(Ah[mf][2]));
            Ah[mf][3] = tfu(f3); Al[mf][3] = tfu(f3 - __uint_as_float(Ah[mf][3]));
        }
        #pragma unroll
        for (int nf = 0; nf < 4; nf++) {
            const float* bp = sv + (8 * ks + t4) * WV_STR + h * HD + 8 * nf + g4;
            unsigned b0 = __float_as_uint(bp[0]);
            unsigned b1 = __float_as_uint(bp[4 * WV_STR]);
            #pragma unroll
            for (int mf = 0; mf < 4; mf++) {
                mma_tf32(oacc[mf][nf], Al[mf], b0, b1);
                mma_tf32(oacc[mf][nf], Ah[mf], b0, b1);
            }
        }
    }

    #pragma unroll
    for (int mf = 0; mf < 4; mf++) {
        const int i0 = 16 * mf + g4;
        const int i1 = i0 + 8;
        const float inv0 = 1.0f / rs0[mf];
        const float inv1 = 1.0f / rs1[mf];
        #pragma unroll
        for (int nf = 0; nf < 4; nf++) {
            const int col = h * HD + 8 * nf + 2 * t4;
            if (i0 < NGT) {
                float2 v; v.x = oacc[mf][nf][0] * inv0; v.y = oacc[mf][nf][1] * inv0;
                *(float2*)(out + (size_t)(w * NGT + i0) * CDIM + col) = v;
            }
            if (i1 < NGT) {
                float2 v; v.x = oacc[mf][nf][2] * inv1; v.y = oacc[mf][nf][3] * inv1;
                *(float2*)(out + (size_t)(w * NGT + i1) * CDIM + col) = v;
            }
        }
    }
}

// ---------------- global-token attention ----------------
__global__ void __launch_bounds__(512)
glob_attn_kernel(const float* __restrict__ xavg, const float* __restrict__ Wq,
                 const float* __restrict__ bq, float* __restrict__ out)
{
    const int b = blockIdx.x;
    const int h = blockIdx.y;
    const int tid  = threadIdx.x;
    const int warp = tid >> 5;
    const int lane = tid & 31;

    __shared__ float qa[32];
    __shared__ float logits[NTPAT];
    __shared__ float red[512];
    __shared__ float ored[16][33];

    if (tid < 32) {
        float acc = bq[h * HD + tid];
        const float* xr = xavg + (size_t)b * CDIM;
        for (int c = 0; c < CDIM; c++)
            acc += xr[c] * Wq[c * CDIM + h * HD + tid];
        qa[tid] = acc;
    }
    __syncthreads();

    const float* Kb = g_Kg + (size_t)b * NTPAT * CDIM + h * HD;
    const float  qv = qa[lane];
    for (int m0 = warp * 4; m0 < NTPAT; m0 += 64) {
        float p0 = qv * Kb[(size_t)(m0 + 0) * CDIM + lane];
        float p1 = qv * Kb[(size_t)(m0 + 1) * CDIM + lane];
        float p2 = qv * Kb[(size_t)(m0 + 2) * CDIM + lane];
        float p3 = qv * Kb[(size_t)(m0 + 3) * CDIM + lane];
        #pragma unroll
        for (int o = 16; o; o >>= 1) {
            p0 += __shfl_down_sync(0xffffffffu, p0, o);
            p1 += __shfl_down_sync(0xffffffffu, p1, o);
            p2 += __shfl_down_sync(0xffffffffu, p2, o);
            p3 += __shfl_down_sync(0xffffffffu, p3, o);
        }
        if (lane == 0) {
            logits[m0 + 0] = p0; logits[m0 + 1] = p1;
            logits[m0 + 2] = p2; logits[m0 + 3] = p3;
        }
    }
    __syncthreads();

    float mx = -1e30f;
    for (int m = tid; m < NTPAT; m += 512) mx = fmaxf(mx, logits[m]);
    red[tid] = mx; __syncthreads();
    for (int s = 256; s; s >>= 1) { if (tid < s) red[tid] = fmaxf(red[tid], red[tid + s]); __syncthreads(); }
    mx = red[0]; __syncthreads();

    float sum = 0.0f;
    for (int m = tid; m < NTPAT; m += 512) {
        float e = expf(logits[m] - mx);
        logits[m] = e;
        sum += e;
    }
    red[tid] = sum; __syncthreads();
    for (int s = 256; s; s >>= 1) { if (tid < s) red[tid] += red[tid + s]; __syncthreads(); }
    sum = red[0];
    __syncthreads();

    const float* Vb = g_Vg + (size_t)b * NTPAT * CDIM + h * HD;
    float acc = 0.0f;
    for (int m0 = warp * 4; m0 < NTPAT; m0 += 64) {
        float v0 = Vb[(size_t)(m0 + 0) * CDIM + lane];
        float v1 = Vb[(size_t)(m0 + 1) * CDIM + lane];
        float v2 = Vb[(size_t)(m0 + 2) * CDIM + lane];
        float v3 = Vb[(size_t)(m0 + 3) * CDIM + lane];
        acc += logits[m0] * v0 + logits[m0 + 1] * v1
             + logits[m0 + 2] * v2 + logits[m0 + 3] * v3;
    }
    ored[warp][lane] = acc;
    __syncthreads();
    if (tid < 32) {
        float a = 0.0f;
        #pragma unroll
        for (int p = 0; p < 16; p++) a += ored[p][tid];
        out[(size_t)b * CDIM + h * HD + tid] = a / sum;
    }
}

// ---------------- launch ----------------
extern "C" void kernel_launch(void* const* d_in, const int* in_sizes, int n_in,
                              void* d_out, int out_size)
{
    const float* x      = (const float*)d_in[0];
    const float* xtotal = (const float*)d_in[1];
    const float* xavg   = (const float*)d_in[2];
    const float* mask   = (const float*)d_in[3];
    const float* Wq     = (const float*)d_in[4];
    const float* bq     = (const float*)d_in[5];
    const float* Wkv    = (const float*)d_in[6];
    const float* bkv    = (const float*)d_in[7];
    const float* btab   = (const float*)d_in[8];
    const int*   ridx   = (const int*)d_in[9];

    float* out     = (float*)d_out;
    float* out_avg = out + (size_t)200704u * 128u;

    cudaFuncSetAttribute(bf16_gemm<0, 0>, cudaFuncAttributeMaxDynamicSharedMemorySize, GEMM_SMEM);
    cudaFuncSetAttribute(bf16_gemm<1, 1>, cudaFuncAttributeMaxDynamicSharedMemorySize, GEMM_SMEM);
    cudaFuncSetAttribute(bf16_gemm<0, 2>, cudaFuncAttributeMaxDynamicSharedMemorySize, GEMM_SMEM);
    cudaFuncSetAttribute(win_attn_mma, cudaFuncAttributeMaxDynamicSharedMemorySize, WIN_SMEM);

    bias_build_kernel<<<(HEADS * NGT * NTOK + 255) / 256, 256>>>(btab, ridx);

    bf16_gemm<0, 0><<<dim3(1, 1568), 256, GEMM_SMEM>>>(x, nullptr, Wq, bq, 128, WQ_SCALE);
    bf16_gemm<1, 1><<<dim3(2, 1600), 256, GEMM_SMEM>>>(x, xavg, Wkv, bkv, 256, 1.0f);
    bf16_gemm<0, 2><<<dim3(2, 1568), 256, GEMM_SMEM>>>(xtotal, nullptr, Wkv, bkv, 256, 1.0f);

    win_attn_mma<<<NWIN, 128, WIN_SMEM>>>(mask, out);
    glob_attn_kernel<<<dim3(BIMG, HEADS), 512>>>(xavg, Wq, bq, out_avg);
}

// round 8
// speedup vs baseline: 1.4611x; 1.1025x over previous
#include <cuda_runtime.h>
#include <cuda_bf16.h>
#include <cuda_fp16.h>

// ---------------- problem dims ----------------
#define NWIN   4096
#define NGT    49
#define NTOK   50
#define CDIM   128
#define HEADS  4
#define HD     32
#define BIMG   64
#define NTPAT  3136
#define WQ_SCALE 0.17677669529663687f   // 32^-0.5

// ---------------- device scratch ----------------
__device__ float g_Q [200704u * 128u];
__device__ float g_Kw[204800u * 128u];
__device__ float g_Vw[204800u * 128u];
__device__ float g_Kg[200704u * 128u];
__device__ float g_Vg[200704u * 128u];
__device__ float g_bias[HEADS * NGT * NTOK];

// ---------------- helpers ----------------
__device__ __forceinline__ void mma_bf16(float* c, const unsigned* a,
                                         unsigned b0, unsigned b1)
{
    asm volatile("mma.sync.aligned.m16n8k16.row.col.f32.bf16.bf16.f32 "
                 "{%0,%1,%2,%3}, {%4,%5,%6,%7}, {%8,%9}, {%0,%1,%2,%3};"
                 : "+f"(c[0]), "+f"(c[1]), "+f"(c[2]), "+f"(c[3])
                 : "r"(a[0]), "r"(a[1]), "r"(a[2]), "r"(a[3]), "r"(b0), "r"(b1));
}

__device__ __forceinline__ void mma_f16(float* c, const unsigned* a,
                                        unsigned b0, unsigned b1)
{
    asm volatile("mma.sync.aligned.m16n8k16.row.col.f32.f16.f16.f32 "
                 "{%0,%1,%2,%3}, {%4,%5,%6,%7}, {%8,%9}, {%0,%1,%2,%3};"
                 : "+f"(c[0]), "+f"(c[1]), "+f"(c[2]), "+f"(c[3])
                 : "r"(a[0]), "r"(a[1]), "r"(a[2]), "r"(a[3]), "r"(b0), "r"(b1));
}

__device__ __forceinline__ void ldsm_x4(unsigned* r, unsigned addr) {
    asm volatile("ldmatrix.sync.aligned.m8n8.x4.shared.b16 {%0,%1,%2,%3}, [%4];"
                 : "=r"(r[0]), "=r"(r[1]), "=r"(r[2]), "=r"(r[3]) : "r"(addr));
}
__device__ __forceinline__ void ldsm_x4_t(unsigned* r, unsigned addr) {
    asm volatile("ldmatrix.sync.aligned.m8n8.x4.trans.shared.b16 {%0,%1,%2,%3}, [%4];"
                 : "=r"(r[0]), "=r"(r[1]), "=r"(r[2]), "=r"(r[3]) : "r"(addr));
}
__device__ __forceinline__ unsigned s2u(const void* p) {
    return (unsigned)__cvta_generic_to_shared(p);
}
__device__ __forceinline__ unsigned pk2(__nv_bfloat16 a, __nv_bfloat16 b) {
    __nv_bfloat162 t(a, b);
    return *reinterpret_cast<unsigned*>(&t);
}
__device__ __forceinline__ unsigned h2pk(float a, float b) {
    __half2 t = __floats2half2_rn(a, b);
    return *reinterpret_cast<unsigned*>(&t);
}

// =====================================================================
// Split-BF16 projection GEMM (R4) + ldmatrix fragment loads.
// =====================================================================
#define SBB_STR 136
#define SAB_STR 40
#define SBB_PL  (128 * SBB_STR)
#define SAB_PL  (128 * SAB_STR)
#define GEMM_SMEM ((2 * SBB_PL + 4 * SAB_PL) * 2)   // 110592 bytes

template<int GATHER, int DST>
__global__ void __launch_bounds__(256, 2)
bf16_gemm(const float* __restrict__ A, const float* __restrict__ Aavg,
          const float* __restrict__ W, const float* __restrict__ bias,
          int N, float alpha)
{
    extern __shared__ __nv_bfloat16 sm[];
    __nv_bfloat16* sBh = sm;
    __nv_bfloat16* sBl = sm + SBB_PL;
    __nv_bfloat16* sA  = sm + 2 * SBB_PL;

    const int tid  = threadIdx.x;
    const int lane = tid & 31;
    const int warp = tid >> 5;
    const int wm   = warp >> 2;
    const int wn   = warp & 3;
    const int g4   = lane >> 2;
    const int t4   = lane & 3;
    const int nblk = blockIdx.x * 128;
    const int by   = blockIdx.y;

    // ldmatrix lane decomposition
    const int lr    = lane & 7;
    const int lt8   = ((lane >> 3) & 1) * 8;
    const int lk8   = (lane >> 4) * 8;
    const int bnoff = ((lane >> 4) & 1) * 8;      // tile>>1 within x4
    const int bk8   = ((lane >> 3) & 1) * 8;      // tile&1

    const int a_row  = tid >> 1;
    const int a_half = (tid & 1) * 16;
    const int m = by * 128 + a_row;
    const float* arow;
    if (GATHER) {
        int w  = m / NTOK;
        int rr = m - w * NTOK;
        arow = (rr < NGT) ? (A    + (size_t)(w * NGT + rr) * CDIM)
                          : (Aavg + (size_t)(w >> 6)       * CDIM);
    } else {
        arow = A + (size_t)m * CDIM;
    }

    // ---- B panel: coalesced column read, [n][k] hi/lo store ----
    {
        const int nloc  = (warp & 3) * 32 + lane;
        const int kbase = (warp >> 2) * 64;
        const float* wp = W + nblk + nloc;
        #pragma unroll
        for (int kg = 0; kg < 16; kg++) {
            const int k = kbase + kg * 4;
            float v0 = wp[(size_t)(k + 0) * N];
            float v1 = wp[(size_t)(k + 1) * N];
            float v2 = wp[(size_t)(k + 2) * N];
            float v3 = wp[(size_t)(k + 3) * N];
            __nv_bfloat16 h0 = __float2bfloat16(v0);
            __nv_bfloat16 h1 = __float2bfloat16(v1);
            __nv_bfloat16 h2 = __float2bfloat16(v2);
            __nv_bfloat16 h3 = __float2bfloat16(v3);
            __nv_bfloat16 l0 = __float2bfloat16(v0 - __bfloat162float(h0));
            __nv_bfloat16 l1 = __float2bfloat16(v1 - __bfloat162float(h1));
            __nv_bfloat16 l2 = __float2bfloat16(v2 - __bfloat162float(h2));
            __nv_bfloat16 l3 = __float2bfloat16(v3 - __bfloat162float(h3));
            *(uint2*)(sBh + nloc * SBB_STR + k) = make_uint2(pk2(h0, h1), pk2(h2, h3));
            *(uint2*)(sBl + nloc * SBB_STR + k) = make_uint2(pk2(l0, l1), pk2(l2, l3));
        }
    }

    // ---- A prologue ----
    float4 areg[4];
    #pragma unroll
    for (int j = 0; j < 4; j++)
        areg[j] = *(const float4*)(arow + a_half + 4 * j);
    {
        __nv_bfloat16* dh = sA + a_row * SAB_STR + a_half;
        __nv_bfloat16* dl = dh + SAB_PL;
        #pragma unroll
        for (int j = 0; j < 4; j++) {
            __nv_bfloat16 h0 = __float2bfloat16(areg[j].x);
            __nv_bfloat16 h1 = __float2bfloat16(areg[j].y);
            __nv_bfloat16 h2 = __float2bfloat16(areg[j].z);
            __nv_bfloat16 h3 = __float2bfloat16(areg[j].w);
            __nv_bfloat16 l0 = __float2bfloat16(areg[j].x - __bfloat162float(h0));
            __nv_bfloat16 l1 = __float2bfloat16(areg[j].y - __bfloat162float(h1));
            __nv_bfloat16 l2 = __float2bfloat16(areg[j].z - __bfloat162float(h2));
            __nv_bfloat16 l3 = __float2bfloat16(areg[j].w - __bfloat162float(h3));
            *(uint2*)(dh + 4 * j) = make_uint2(pk2(h0, h1), pk2(h2, h3));
            *(uint2*)(dl + 4 * j) = make_uint2(pk2(l0, l1), pk2(l2, l3));
        }
    }
    __syncthreads();

    float acc[4][4][4];
    #pragma unroll
    for (int mf = 0; mf < 4; mf++)
        #pragma unroll
        for (int nf = 0; nf < 4; nf++)
            #pragma unroll
            for (int c = 0; c < 4; c++) acc[mf][nf][c] = 0.0f;

    const int a_m0 = wm * 64;
    const int b_n0 = wn * 32;

    for (int kt = 0; kt < 4; kt++) {
        if (kt < 3) {
            #pragma unroll
            for (int j = 0; j < 4; j++)
                areg[j] = *(const float4*)(arow + (kt + 1) * 32 + a_half + 4 * j);
        }
        const __nv_bfloat16* Ahp = sA + (kt & 1) * (2 * SAB_PL);

        #pragma unroll
        for (int st = 0; st < 2; st++) {
            const int kloc  = st * 16;
            const int kglob = kt * 32 + kloc;
            unsigned ah[4][4], al[4][4];
            #pragma unroll
            for (int mf = 0; mf < 4; mf++) {
                const __nv_bfloat16* pa_ = Ahp + (a_m0 + 16 * mf + lt8 + lr) * SAB_STR + kloc + lk8;
                ldsm_x4(ah[mf], s2u(pa_));
                ldsm_x4(al[mf], s2u(pa_ + SAB_PL));
            }
            unsigned bh[4][2], bl[4][2];
            #pragma unroll
            for (int p = 0; p < 2; p++) {
                const __nv_bfloat16* pb = sBh + (b_n0 + 16 * p + bnoff + lr) * SBB_STR + kglob + bk8;
                unsigned t[4];
                ldsm_x4(t, s2u(pb));
                bh[2*p][0] = t[0]; bh[2*p][1] = t[1];
                bh[2*p+1][0] = t[2]; bh[2*p+1][1] = t[3];
                ldsm_x4(t, s2u(pb + SBB_PL));
                bl[2*p][0] = t[0]; bl[2*p][1] = t[1];
                bl[2*p+1][0] = t[2]; bl[2*p+1][1] = t[3];
            }
            #pragma unroll
            for (int nf = 0; nf < 4; nf++)
                #pragma unroll
                for (int mf = 0; mf < 4; mf++) {
                    mma_bf16(acc[mf][nf], ah[mf], bl[nf][0], bl[nf][1]);
                    mma_bf16(acc[mf][nf], al[mf], bh[nf][0], bh[nf][1]);
                    mma_bf16(acc[mf][nf], ah[mf], bh[nf][0], bh[nf][1]);
                }
        }

        if (kt < 3) {
            __syncthreads();
            __nv_bfloat16* dh = sA + ((kt + 1) & 1) * (2 * SAB_PL) + a_row * SAB_STR + a_half;
            __nv_bfloat16* dl = dh + SAB_PL;
            #pragma unroll
            for (int j = 0; j < 4; j++) {
                __nv_bfloat16 h0 = __float2bfloat16(areg[j].x);
                __nv_bfloat16 h1 = __float2bfloat16(areg[j].y);
                __nv_bfloat16 h2 = __float2bfloat16(areg[j].z);
                __nv_bfloat16 h3 = __float2bfloat16(areg[j].w);
                __nv_bfloat16 l0 = __float2bfloat16(areg[j].x - __bfloat162float(h0));
                __nv_bfloat16 l1 = __float2bfloat16(areg[j].y - __bfloat162float(h1));
                __nv_bfloat16 l2 = __float2bfloat16(areg[j].z - __bfloat162float(h2));
                __nv_bfloat16 l3 = __float2bfloat16(areg[j].w - __bfloat162float(h3));
                *(uint2*)(dh + 4 * j) = make_uint2(pk2(h0, h1), pk2(h2, h3));
                *(uint2*)(dl + 4 * j) = make_uint2(pk2(l0, l1), pk2(l2, l3));
            }
            __syncthreads();
        }
    }

    float* Cout;
    if (DST == 0)       Cout = g_Q;
    else if (DST == 1)  Cout = (blockIdx.x == 0) ? g_Kw : g_Vw;
    else                Cout = (blockIdx.x == 0) ? g_Kg : g_Vg;

    #pragma unroll
    for (int mf = 0; mf < 4; mf++) {
        int row0 = by * 128 + a_m0 + mf * 16 + g4;
        #pragma unroll
        for (int nf = 0; nf < 4; nf++) {
            int ncol = b_n0 + nf * 8 + 2 * t4;
            float bb0 = bias[nblk + ncol];
            float bb1 = bias[nblk + ncol + 1];
            float2 v0, v1;
            v0.x = (acc[mf][nf][0] + bb0) * alpha;
            v0.y = (acc[mf][nf][1] + bb1) * alpha;
            v1.x = (acc[mf][nf][2] + bb0) * alpha;
            v1.y = (acc[mf][nf][3] + bb1) * alpha;
            *(float2*)(Cout + (size_t)row0 * 128 + ncol)       = v0;
            *(float2*)(Cout + (size_t)(row0 + 8) * 128 + ncol) = v1;
        }
    }
}

// ---------------- bias gather ----------------
__global__ void bias_build_kernel(const float* __restrict__ table,
                                  const int* __restrict__ ridx)
{
    int idx = blockIdx.x * 256 + threadIdx.x;
    if (idx < HEADS * NGT * NTOK) {
        int h  = idx / (NGT * NTOK);
        int ij = idx - h * (NGT * NTOK);
        g_bias[idx] = table[ridx[ij] * HEADS + h];
    }
}

// =====================================================================
// Window attention, fp16 MMA pipeline.
// S = QK^T (f16 k16), softmax in regs, P packed directly into A-frags
// (C-layout == A-layout for f16 k16), O = P V with ldmatrix.trans V hi/lo.
// =====================================================================
#define WH_STR 136                       // halves per row (272B, 4-bank shift)
#define WPLANE (64 * WH_STR)             // halves per plane
#define WIN_SMEM (4 * WPLANE * 2)        // 69632 bytes

__global__ void __launch_bounds__(128)
win_attn_mma(const float* __restrict__ mask, float* __restrict__ out)
{
    extern __shared__ __half smh[];
    __half* sQ  = smh;
    __half* sK  = smh + WPLANE;
    __half* sVh = smh + 2 * WPLANE;
    __half* sVl = smh + 3 * WPLANE;

    const int w    = blockIdx.x;
    const int tid  = threadIdx.x;
    const int h    = tid >> 5;
    const int lane = tid & 31;
    const int g4   = lane >> 2;
    const int t4   = lane & 3;

    // zero pad rows: Q 49..63 (255 uint4), K/V 50..63 (238 uint4 each)
    {
        uint4 z = make_uint4(0, 0, 0, 0);
        uint4* zq = (uint4*)(sQ + 49 * WH_STR);
        uint4* zk = (uint4*)(sK + 50 * WH_STR);
        uint4* zh = (uint4*)(sVh + 50 * WH_STR);
        uint4* zl = (uint4*)(sVl + 50 * WH_STR);
        for (int i = tid; i < 255; i += 128) zq[i] = z;
        for (int i = tid; i < 238; i += 128) { zk[i] = z; zh[i] = z; zl[i] = z; }
    }

    // fill Q
    for (int idx = tid; idx < 49 * 32; idx += 128) {
        int r = idx >> 5, c4 = (idx & 31) << 2;
        float4 v = *(const float4*)(g_Q + (size_t)(w * NGT + r) * CDIM + c4);
        *(uint2*)(sQ + r * WH_STR + c4) = make_uint2(h2pk(v.x, v.y), h2pk(v.z, v.w));
    }
    // fill K, V(hi/lo)
    for (int idx = tid; idx < 50 * 32; idx += 128) {
        int r = idx >> 5, c4 = (idx & 31) << 2;
        size_t off = (size_t)(w * NTOK + r) * CDIM + c4;
        float4 kk = *(const float4*)(g_Kw + off);
        float4 vv = *(const float4*)(g_Vw + off);
        *(uint2*)(sK + r * WH_STR + c4) = make_uint2(h2pk(kk.x, kk.y), h2pk(kk.z, kk.w));
        __half v0 = __float2half_rn(vv.x), v1 = __float2half_rn(vv.y);
        __half v2 = __float2half_rn(vv.z), v3 = __float2half_rn(vv.w);
        __half2 hA(v0, v1), hB(v2, v3);
        *(uint2*)(sVh + r * WH_STR + c4) =
            make_uint2(*(unsigned*)&hA, *(unsigned*)&hB);
        *(uint2*)(sVl + r * WH_STR + c4) =
            make_uint2(h2pk(vv.x - __half2float(v0), vv.y - __half2float(v1)),
                       h2pk(vv.z - __half2float(v2), vv.w - __half2float(v3)));
    }
    __syncthreads();

    // ---- S = Q K^T : f16 m16n8k16, 2 k-steps over head dim 32 ----
    float sacc[4][7][4];
    #pragma unroll
    for (int mf = 0; mf < 4; mf++)
        #pragma unroll
        for (int nf = 0; nf < 7; nf++)
            #pragma unroll
            for (int c = 0; c < 4; c++) sacc[mf][nf][c] = 0.0f;

    #pragma unroll
    for (int ks = 0; ks < 2; ks++) {
        const int kc = h * HD + ks * 16 + 2 * t4;
        unsigned a[4][4];
        #pragma unroll
        for (int mf = 0; mf < 4; mf++) {
            const __half* ap = sQ + (16 * mf + g4) * WH_STR + kc;
            a[mf][0] = *(const unsigned*)(ap);
            a[mf][1] = *(const unsigned*)(ap + 8 * WH_STR);
            a[mf][2] = *(const unsigned*)(ap + 8);
            a[mf][3] = *(const unsigned*)(ap + 8 * WH_STR + 8);
        }
        #pragma unroll
        for (int nf = 0; nf < 7; nf++) {
            const __half* bp = sK + (8 * nf + g4) * WH_STR + kc;
            unsigned b0 = *(const unsigned*)(bp);
            unsigned b1 = *(const unsigned*)(bp + 8);
            #pragma unroll
            for (int mf = 0; mf < 4; mf++)
                mma_f16(sacc[mf][nf], a[mf], b0, b1);
        }
    }

    // ---- bias + mask + softmax ----
    const float* bptr = g_bias + h * (NGT * NTOK);
    const float* mptr = mask + (size_t)(w & 63) * (NGT * NTOK);
    float rs0[4], rs1[4];

    #pragma unroll
    for (int mf = 0; mf < 4; mf++) {
        const int i0 = 16 * mf + g4;
        const int i1 = i0 + 8;
        float m0 = -1e30f, m1 = -1e30f;
        #pragma unroll
        for (int nf = 0; nf < 7; nf++) {
            const int j0 = 8 * nf + 2 * t4;
            const int j1 = j0 + 1;
            float s0 = (i0 < NGT && j0 < NTOK) ? sacc[mf][nf][0] + bptr[i0 * 50 + j0] + mptr[i0 * 50 + j0] : -1e30f;
            float s1 = (i0 < NGT && j1 < NTOK) ? sacc[mf][nf][1] + bptr[i0 * 50 + j1] + mptr[i0 * 50 + j1] : -1e30f;
            float s2 = (i1 < NGT && j0 < NTOK) ? sacc[mf][nf][2] + bptr[i1 * 50 + j0] + mptr[i1 * 50 + j0] : -1e30f;
            float s3 = (i1 < NGT && j1 < NTOK) ? sacc[mf][nf][3] + bptr[i1 * 50 + j1] + mptr[i1 * 50 + j1] : -1e30f;
            sacc[mf][nf][0] = s0; sacc[mf][nf][1] = s1;
            sacc[mf][nf][2] = s2; sacc[mf][nf][3] = s3;
            m0 = fmaxf(m0, fmaxf(s0, s1));
            m1 = fmaxf(m1, fmaxf(s2, s3));
        }
        m0 = fmaxf(m0, __shfl_xor_sync(0xffffffffu, m0, 1));
        m0 = fmaxf(m0, __shfl_xor_sync(0xffffffffu, m0, 2));
        m1 = fmaxf(m1, __shfl_xor_sync(0xffffffffu, m1, 1));
        m1 = fmaxf(m1, __shfl_xor_sync(0xffffffffu, m1, 2));
        float r0 = 0.0f, r1 = 0.0f;
        #pragma unroll
        for (int nf = 0; nf < 7; nf++) {
            float p0 = __expf(sacc[mf][nf][0] - m0);
            float p1 = __expf(sacc[mf][nf][1] - m0);
            float p2 = __expf(sacc[mf][nf][2] - m1);
            float p3 = __expf(sacc[mf][nf][3] - m1);
            sacc[mf][nf][0] = p0; sacc[mf][nf][1] = p1;
            sacc[mf][nf][2] = p2; sacc[mf][nf][3] = p3;
            r0 += p0 + p1;
            r1 += p2 + p3;
        }
        r0 += __shfl_xor_sync(0xffffffffu, r0, 1);
        r0 += __shfl_xor_sync(0xffffffffu, r0, 2);
        r1 += __shfl_xor_sync(0xffffffffu, r1, 1);
        r1 += __shfl_xor_sync(0xffffffffu, r1, 2);
        rs0[mf] = r0; rs1[mf] = r1;
    }

    // ---- pack P into fp16 A-fragments (no shuffles: C-layout == A-layout) ----
    unsigned pa[4][4][4];
    #pragma unroll
    for (int mf = 0; mf < 4; mf++) {
        #pragma unroll
        for (int ks = 0; ks < 3; ks++) {
            pa[ks][mf][0] = h2pk(sacc[mf][2*ks][0],   sacc[mf][2*ks][1]);
            pa[ks][mf][1] = h2pk(sacc[mf][2*ks][2],   sacc[mf][2*ks][3]);
            pa[ks][mf][2] = h2pk(sacc[mf][2*ks+1][0], sacc[mf][2*ks+1][1]);
            pa[ks][mf][3] = h2pk(sacc[mf][2*ks+1][2], sacc[mf][2*ks+1][3]);
        }
        pa[3][mf][0] = h2pk(sacc[mf][6][0], sacc[mf][6][1]);
        pa[3][mf][1] = h2pk(sacc[mf][6][2], sacc[mf][6][3]);
        pa[3][mf][2] = 0u;
        pa[3][mf][3] = 0u;
    }

    // ---- O = P V : f16 m16n8k16, V via ldmatrix.trans, hi/lo split ----
    float oacc[4][4][4];
    #pragma unroll
    for (int mf = 0; mf < 4; mf++)
        #pragma unroll
        for (int nf = 0; nf < 4; nf++)
            #pragma unroll
            for (int c = 0; c < 4; c++) oacc[mf][nf][c] = 0.0f;

    const int lr    = lane & 7;
    const int vbk   = ((lane >> 3) & 1) * 8;      // tile&1 -> token +8
    const int vnoff = ((lane >> 4) & 1) * 8;      // tile>>1 -> nf within pair

    #pragma unroll
    for (int ks = 0; ks < 4; ks++) {
        unsigned bh[4][2], bl[4][2];
        #pragma unroll
        for (int p = 0; p < 2; p++) {
            const __half* vp = sVh + (ks * 16 + vbk + lr) * WH_STR + h * HD + 16 * p + vnoff;
            unsigned t[4];
            ldsm_x4_t(t, s2u(vp));
            bh[2*p][0] = t[0]; bh[2*p][1] = t[1];
            bh[2*p+1][0] = t[2]; bh[2*p+1][1] = t[3];
            ldsm_x4_t(t, s2u(vp + WPLANE));       // sVl is next plane
            bl[2*p][0] = t[0]; bl[2*p][1] = t[1];
            bl[2*p+1][0] = t[2]; bl[2*p+1][1] = t[3];
        }
        #pragma unroll
        for (int nf = 0; nf < 4; nf++)
            #pragma unroll
            for (int mf = 0; mf < 4; mf++) {
                mma_f16(oacc[mf][nf], pa[ks][mf], bh[nf][0], bh[nf][1]);
                mma_f16(oacc[mf][nf], pa[ks][mf], bl[nf][0], bl[nf][1]);
            }
    }

    // ---- normalize + store ----
    #pragma unroll
    for (int mf = 0; mf < 4; mf++) {
        const int i0 = 16 * mf + g4;
        const int i1 = i0 + 8;
        const float inv0 = 1.0f / rs0[mf];
        const float inv1 = 1.0f / rs1[mf];
        #pragma unroll
        for (int nf = 0; nf < 4; nf++) {
            const int col = h * HD + 8 * nf + 2 * t4;
            if (i0 < NGT) {
                float2 v; v.x = oacc[mf][nf][0] * inv0; v.y = oacc[mf][nf][1] * inv0;
                *(float2*)(out + (size_t)(w * NGT + i0) * CDIM + col) = v;
            }
            if (i1 < NGT) {
                float2 v; v.x = oacc[mf][nf][2] * inv1; v.y = oacc[mf][nf][3] * inv1;
                *(float2*)(out + (size_t)(w * NGT + i1) * CDIM + col) = v;
            }
        }
    }
}

// ---------------- global-token attention ----------------
__global__ void __launch_bounds__(512)
glob_attn_kernel(const float* __restrict__ xavg, const float* __restrict__ Wq,
                 const float* __restrict__ bq, float* __restrict__ out)
{
    const int b = blockIdx.x;
    const int h = blockIdx.y;
    const int tid  = threadIdx.x;
    const int warp = tid >> 5;
    const int lane = tid & 31;

    __shared__ float qa[32];
    __shared__ float logits[NTPAT];
    __shared__ float red[512];
    __shared__ float ored[16][33];

    if (tid < 32) {
        float acc = bq[h * HD + tid];
        const float* xr = xavg + (size_t)b * CDIM;
        for (int c = 0; c < CDIM; c++)
            acc += xr[c] * Wq[c * CDIM + h * HD + tid];
        qa[tid] = acc;
    }
    __syncthreads();

    const float* Kb = g_Kg + (size_t)b * NTPAT * CDIM + h * HD;
    const float  qv = qa[lane];
    for (int m0 = warp * 4; m0 < NTPAT; m0 += 64) {
        float p0 = qv * Kb[(size_t)(m0 + 0) * CDIM + lane];
        float p1 = qv * Kb[(size_t)(m0 + 1) * CDIM + lane];
        float p2 = qv * Kb[(size_t)(m0 + 2) * CDIM + lane];
        float p3 = qv * Kb[(size_t)(m0 + 3) * CDIM + lane];
        #pragma unroll
        for (int o = 16; o; o >>= 1) {
            p0 += __shfl_down_sync(0xffffffffu, p0, o);
            p1 += __shfl_down_sync(0xffffffffu, p1, o);
            p2 += __shfl_down_sync(0xffffffffu, p2, o);
            p3 += __shfl_down_sync(0xffffffffu, p3, o);
        }
        if (lane == 0) {
            logits[m0 + 0] = p0; logits[m0 + 1] = p1;
            logits[m0 + 2] = p2; logits[m0 + 3] = p3;
        }
    }
    __syncthreads();

    float mx = -1e30f;
    for (int m = tid; m < NTPAT; m += 512) mx = fmaxf(mx, logits[m]);
    red[tid] = mx; __syncthreads();
    for (int s = 256; s; s >>= 1) { if (tid < s) red[tid] = fmaxf(red[tid], red[tid + s]); __syncthreads(); }
    mx = red[0]; __syncthreads();

    float sum = 0.0f;
    for (int m = tid; m < NTPAT; m += 512) {
        float e = expf(logits[m] - mx);
        logits[m] = e;
        sum += e;
    }
    red[tid] = sum; __syncthreads();
    for (int s = 256; s; s >>= 1) { if (tid < s) red[tid] += red[tid + s]; __syncthreads(); }
    sum = red[0];
    __syncthreads();

    const float* Vb = g_Vg + (size_t)b * NTPAT * CDIM + h * HD;
    float acc = 0.0f;
    for (int m0 = warp * 4; m0 < NTPAT; m0 += 64) {
        float v0 = Vb[(size_t)(m0 + 0) * CDIM + lane];
        float v1 = Vb[(size_t)(m0 + 1) * CDIM + lane];
        float v2 = Vb[(size_t)(m0 + 2) * CDIM + lane];
        float v3 = Vb[(size_t)(m0 + 3) * CDIM + lane];
        acc += logits[m0] * v0 + logits[m0 + 1] * v1
             + logits[m0 + 2] * v2 + logits[m0 + 3] * v3;
    }
    ored[warp][lane] = acc;
    __syncthreads();
    if (tid < 32) {
        float a = 0.0f;
        #pragma unroll
        for (int p = 0; p < 16; p++) a += ored[p][tid];
        out[(size_t)b * CDIM + h * HD + tid] = a / sum;
    }
}

// ---------------- launch ----------------
extern "C" void kernel_launch(void* const* d_in, const int* in_sizes, int n_in,
                              void* d_out, int out_size)
{
    const float* x      = (const float*)d_in[0];
    const float* xtotal = (const float*)d_in[1];
    const float* xavg   = (const float*)d_in[2];
    const float* mask   = (const float*)d_in[3];
    const float* Wq     = (const float*)d_in[4];
    const float* bq     = (const float*)d_in[5];
    const float* Wkv    = (const float*)d_in[6];
    const float* bkv    = (const float*)d_in[7];
    const float* btab   = (const float*)d_in[8];
    const int*   ridx   = (const int*)d_in[9];

    float* out     = (float*)d_out;
    float* out_avg = out + (size_t)200704u * 128u;

    cudaFuncSetAttribute(bf16_gemm<0, 0>, cudaFuncAttributeMaxDynamicSharedMemorySize, GEMM_SMEM);
    cudaFuncSetAttribute(bf16_gemm<1, 1>, cudaFuncAttributeMaxDynamicSharedMemorySize, GEMM_SMEM);
    cudaFuncSetAttribute(bf16_gemm<0, 2>, cudaFuncAttributeMaxDynamicSharedMemorySize, GEMM_SMEM);
    cudaFuncSetAttribute(win_attn_mma, cudaFuncAttributeMaxDynamicSharedMemorySize, WIN_SMEM);

    bias_build_kernel<<<(HEADS * NGT * NTOK + 255) / 256, 256>>>(btab, ridx);

    bf16_gemm<0, 0><<<dim3(1, 1568), 256, GEMM_SMEM>>>(x, nullptr, Wq, bq, 128, WQ_SCALE);
    bf16_gemm<1, 1><<<dim3(2, 1600), 256, GEMM_SMEM>>>(x, xavg, Wkv, bkv, 256, 1.0f);
    bf16_gemm<0, 2><<<dim3(2, 1568), 256, GEMM_SMEM>>>(xtotal, nullptr, Wkv, bkv, 256, 1.0f);

    win_attn_mma<<<NWIN, 128, WIN_SMEM>>>(mask, out);
    glob_attn_kernel<<<dim3(BIMG, HEADS), 512>>>(xavg, Wq, bq, out_avg);
}

// round 9
// speedup vs baseline: 1.8357x; 1.2564x over previous
#include <cuda_runtime.h>
#include <cuda_bf16.h>
#include <cuda_fp16.h>

// ---------------- problem dims ----------------
#define NWIN   4096
#define NGT    49
#define NTOK   50
#define CDIM   128
#define HEADS  4
#define HD     32
#define BIMG   64
#define NTPAT  3136
#define WQ_SCALE 0.17677669529663687f   // 32^-0.5

// ---------------- device scratch ----------------
__device__ __half g_Qh [200704u * 128u];   // window q (scaled), fp16
__device__ __half g_Kwh[204800u * 128u];   // window K fp16
__device__ __half g_Vwh[204800u * 128u];   // window V hi fp16
__device__ __half g_Vwl[204800u * 128u];   // window V lo fp16
__device__ float  g_Kg [200704u * 128u];   // global K fp32
__device__ float  g_Vg [200704u * 128u];   // global V fp32
__device__ float  g_bias[HEADS * NGT * NTOK];

// ---------------- helpers ----------------
__device__ __forceinline__ void mma_bf16(float* c, const unsigned* a,
                                         unsigned b0, unsigned b1)
{
    asm volatile("mma.sync.aligned.m16n8k16.row.col.f32.bf16.bf16.f32 "
                 "{%0,%1,%2,%3}, {%4,%5,%6,%7}, {%8,%9}, {%0,%1,%2,%3};"
                 : "+f"(c[0]), "+f"(c[1]), "+f"(c[2]), "+f"(c[3])
                 : "r"(a[0]), "r"(a[1]), "r"(a[2]), "r"(a[3]), "r"(b0), "r"(b1));
}
__device__ __forceinline__ void mma_f16(float* c, const unsigned* a,
                                        unsigned b0, unsigned b1)
{
    asm volatile("mma.sync.aligned.m16n8k16.row.col.f32.f16.f16.f32 "
                 "{%0,%1,%2,%3}, {%4,%5,%6,%7}, {%8,%9}, {%0,%1,%2,%3};"
                 : "+f"(c[0]), "+f"(c[1]), "+f"(c[2]), "+f"(c[3])
                 : "r"(a[0]), "r"(a[1]), "r"(a[2]), "r"(a[3]), "r"(b0), "r"(b1));
}
__device__ __forceinline__ void ldsm_x4(unsigned* r, unsigned addr) {
    asm volatile("ldmatrix.sync.aligned.m8n8.x4.shared.b16 {%0,%1,%2,%3}, [%4];"
                 : "=r"(r[0]), "=r"(r[1]), "=r"(r[2]), "=r"(r[3]) : "r"(addr));
}
__device__ __forceinline__ void ldsm_x4_t(unsigned* r, unsigned addr) {
    asm volatile("ldmatrix.sync.aligned.m8n8.x4.trans.shared.b16 {%0,%1,%2,%3}, [%4];"
                 : "=r"(r[0]), "=r"(r[1]), "=r"(r[2]), "=r"(r[3]) : "r"(addr));
}
__device__ __forceinline__ unsigned s2u(const void* p) {
    return (unsigned)__cvta_generic_to_shared(p);
}
__device__ __forceinline__ unsigned pk2(__nv_bfloat16 a, __nv_bfloat16 b) {
    __nv_bfloat162 t(a, b);
    return *reinterpret_cast<unsigned*>(&t);
}
__device__ __forceinline__ unsigned h2pk(float a, float b) {
    __half2 t = __floats2half2_rn(a, b);
    return *reinterpret_cast<unsigned*>(&t);
}

// =====================================================================
// Split-BF16 projection GEMM + ldmatrix fragment loads.
// DST=0 -> g_Qh (half); DST=1 -> g_Kwh / g_Vwh+g_Vwl (half); DST=2 -> g_Kg/g_Vg (f32)
// =====================================================================
#define SBB_STR 136
#define SAB_STR 40
#define SBB_PL  (128 * SBB_STR)
#define SAB_PL  (128 * SAB_STR)
#define GEMM_SMEM ((2 * SBB_PL + 4 * SAB_PL) * 2)   // 110592 bytes

template<int GATHER, int DST>
__global__ void __launch_bounds__(256, 2)
bf16_gemm(const float* __restrict__ A, const float* __restrict__ Aavg,
          const float* __restrict__ W, const float* __restrict__ bias,
          int N, float alpha)
{
    extern __shared__ __nv_bfloat16 sm[];
    __nv_bfloat16* sBh = sm;
    __nv_bfloat16* sBl = sm + SBB_PL;
    __nv_bfloat16* sA  = sm + 2 * SBB_PL;

    const int tid  = threadIdx.x;
    const int lane = tid & 31;
    const int warp = tid >> 5;
    const int wm   = warp >> 2;
    const int wn   = warp & 3;
    const int g4   = lane >> 2;
    const int t4   = lane & 3;
    const int nblk = blockIdx.x * 128;
    const int by   = blockIdx.y;

    const int lr    = lane & 7;
    const int lt8   = ((lane >> 3) & 1) * 8;
    const int lk8   = (lane >> 4) * 8;
    const int bnoff = ((lane >> 4) & 1) * 8;
    const int bk8   = ((lane >> 3) & 1) * 8;

    const int a_row  = tid >> 1;
    const int a_half = (tid & 1) * 16;
    const int m = by * 128 + a_row;
    const float* arow;
    if (GATHER) {
        int w  = m / NTOK;
        int rr = m - w * NTOK;
        arow = (rr < NGT) ? (A    + (size_t)(w * NGT + rr) * CDIM)
                          : (Aavg + (size_t)(w >> 6)       * CDIM);
    } else {
        arow = A + (size_t)m * CDIM;
    }

    // ---- B panel: coalesced column read, [n][k] hi/lo store ----
    {
        const int nloc  = (warp & 3) * 32 + lane;
        const int kbase = (warp >> 2) * 64;
        const float* wp = W + nblk + nloc;
        #pragma unroll
        for (int kg = 0; kg < 16; kg++) {
            const int k = kbase + kg * 4;
            float v0 = wp[(size_t)(k + 0) * N];
            float v1 = wp[(size_t)(k + 1) * N];
            float v2 = wp[(size_t)(k + 2) * N];
            float v3 = wp[(size_t)(k + 3) * N];
            __nv_bfloat16 h0 = __float2bfloat16(v0);
            __nv_bfloat16 h1 = __float2bfloat16(v1);
            __nv_bfloat16 h2 = __float2bfloat16(v2);
            __nv_bfloat16 h3 = __float2bfloat16(v3);
            __nv_bfloat16 l0 = __float2bfloat16(v0 - __bfloat162float(h0));
            __nv_bfloat16 l1 = __float2bfloat16(v1 - __bfloat162float(h1));
            __nv_bfloat16 l2 = __float2bfloat16(v2 - __bfloat162float(h2));
            __nv_bfloat16 l3 = __float2bfloat16(v3 - __bfloat162float(h3));
            *(uint2*)(sBh + nloc * SBB_STR + k) = make_uint2(pk2(h0, h1), pk2(h2, h3));
            *(uint2*)(sBl + nloc * SBB_STR + k) = make_uint2(pk2(l0, l1), pk2(l2, l3));
        }
    }

    // ---- A prologue ----
    float4 areg[4];
    #pragma unroll
    for (int j = 0; j < 4; j++)
        areg[j] = *(const float4*)(arow + a_half + 4 * j);
    {
        __nv_bfloat16* dh = sA + a_row * SAB_STR + a_half;
        __nv_bfloat16* dl = dh + SAB_PL;
        #pragma unroll
        for (int j = 0; j < 4; j++) {
            __nv_bfloat16 h0 = __float2bfloat16(areg[j].x);
            __nv_bfloat16 h1 = __float2bfloat16(areg[j].y);
            __nv_bfloat16 h2 = __float2bfloat16(areg[j].z);
            __nv_bfloat16 h3 = __float2bfloat16(areg[j].w);
            __nv_bfloat16 l0 = __float2bfloat16(areg[j].x - __bfloat162float(h0));
            __nv_bfloat16 l1 = __float2bfloat16(areg[j].y - __bfloat162float(h1));
            __nv_bfloat16 l2 = __float2bfloat16(areg[j].z - __bfloat162float(h2));
            __nv_bfloat16 l3 = __float2bfloat16(areg[j].w - __bfloat162float(h3));
            *(uint2*)(dh + 4 * j) = make_uint2(pk2(h0, h1), pk2(h2, h3));
            *(uint2*)(dl + 4 * j) = make_uint2(pk2(l0, l1), pk2(l2, l3));
        }
    }
    __syncthreads();

    float acc[4][4][4];
    #pragma unroll
    for (int mf = 0; mf < 4; mf++)
        #pragma unroll
        for (int nf = 0; nf < 4; nf++)
            #pragma unroll
            for (int c = 0; c < 4; c++) acc[mf][nf][c] = 0.0f;

    const int a_m0 = wm * 64;
    const int b_n0 = wn * 32;

    for (int kt = 0; kt < 4; kt++) {
        if (kt < 3) {
            #pragma unroll
            for (int j = 0; j < 4; j++)
                areg[j] = *(const float4*)(arow + (kt + 1) * 32 + a_half + 4 * j);
        }
        const __nv_bfloat16* Ahp = sA + (kt & 1) * (2 * SAB_PL);

        #pragma unroll
        for (int st = 0; st < 2; st++) {
            const int kloc  = st * 16;
            const int kglob = kt * 32 + kloc;
            unsigned ah[4][4], al[4][4];
            #pragma unroll
            for (int mf = 0; mf < 4; mf++) {
                const __nv_bfloat16* pa_ = Ahp + (a_m0 + 16 * mf + lt8 + lr) * SAB_STR + kloc + lk8;
                ldsm_x4(ah[mf], s2u(pa_));
                ldsm_x4(al[mf], s2u(pa_ + SAB_PL));
            }
            unsigned bh[4][2], bl[4][2];
            #pragma unroll
            for (int p = 0; p < 2; p++) {
                const __nv_bfloat16* pb = sBh + (b_n0 + 16 * p + bnoff + lr) * SBB_STR + kglob + bk8;
                unsigned t[4];
                ldsm_x4(t, s2u(pb));
                bh[2*p][0] = t[0]; bh[2*p][1] = t[1];
                bh[2*p+1][0] = t[2]; bh[2*p+1][1] = t[3];
                ldsm_x4(t, s2u(pb + SBB_PL));
                bl[2*p][0] = t[0]; bl[2*p][1] = t[1];
                bl[2*p+1][0] = t[2]; bl[2*p+1][1] = t[3];
            }
            #pragma unroll
            for (int nf = 0; nf < 4; nf++)
                #pragma unroll
                for (int mf = 0; mf < 4; mf++) {
                    mma_bf16(acc[mf][nf], ah[mf], bl[nf][0], bl[nf][1]);
                    mma_bf16(acc[mf][nf], al[mf], bh[nf][0], bh[nf][1]);
                    mma_bf16(acc[mf][nf], ah[mf], bh[nf][0], bh[nf][1]);
                }
        }

        if (kt < 3) {
            // single barrier per k-tile: writers of buf[(kt+1)&1] are ordered
            // behind all readers (iteration kt-1) by the previous barrier.
            __nv_bfloat16* dh = sA + ((kt + 1) & 1) * (2 * SAB_PL) + a_row * SAB_STR + a_half;
            __nv_bfloat16* dl = dh + SAB_PL;
            #pragma unroll
            for (int j = 0; j < 4; j++) {
                __nv_bfloat16 h0 = __float2bfloat16(areg[j].x);
                __nv_bfloat16 h1 = __float2bfloat16(areg[j].y);
                __nv_bfloat16 h2 = __float2bfloat16(areg[j].z);
                __nv_bfloat16 h3 = __float2bfloat16(areg[j].w);
                __nv_bfloat16 l0 = __float2bfloat16(areg[j].x - __bfloat162float(h0));
                __nv_bfloat16 l1 = __float2bfloat16(areg[j].y - __bfloat162float(h1));
                __nv_bfloat16 l2 = __float2bfloat16(areg[j].z - __bfloat162float(h2));
                __nv_bfloat16 l3 = __float2bfloat16(areg[j].w - __bfloat162float(h3));
                *(uint2*)(dh + 4 * j) = make_uint2(pk2(h0, h1), pk2(h2, h3));
                *(uint2*)(dl + 4 * j) = make_uint2(pk2(l0, l1), pk2(l2, l3));
            }
            __syncthreads();
        }
    }

    // ---- epilogue ----
    #pragma unroll
    for (int mf = 0; mf < 4; mf++) {
        int row0 = by * 128 + a_m0 + mf * 16 + g4;
        #pragma unroll
        for (int nf = 0; nf < 4; nf++) {
            int ncol = b_n0 + nf * 8 + 2 * t4;
            float bb0 = bias[nblk + ncol];
            float bb1 = bias[nblk + ncol + 1];
            float v00 = (acc[mf][nf][0] + bb0) * alpha;
            float v01 = (acc[mf][nf][1] + bb1) * alpha;
            float v10 = (acc[mf][nf][2] + bb0) * alpha;
            float v11 = (acc[mf][nf][3] + bb1) * alpha;
            if (DST == 2) {
                float* Cout = (blockIdx.x == 0) ? g_Kg : g_Vg;
                *(float2*)(Cout + (size_t)row0 * 128 + ncol)       = make_float2(v00, v01);
                *(float2*)(Cout + (size_t)(row0 + 8) * 128 + ncol) = make_float2(v10, v11);
            } else if (DST == 0) {
                *(unsigned*)(g_Qh + (size_t)row0 * 128 + ncol)       = h2pk(v00, v01);
                *(unsigned*)(g_Qh + (size_t)(row0 + 8) * 128 + ncol) = h2pk(v10, v11);
            } else {
                if (blockIdx.x == 0) {
                    *(unsigned*)(g_Kwh + (size_t)row0 * 128 + ncol)       = h2pk(v00, v01);
                    *(unsigned*)(g_Kwh + (size_t)(row0 + 8) * 128 + ncol) = h2pk(v10, v11);
                } else {
                    __half h00 = __float2half_rn(v00), h01 = __float2half_rn(v01);
                    __half h10 = __float2half_rn(v10), h11 = __float2half_rn(v11);
                    __half2 p0(h00, h01), p1(h10, h11);
                    *(unsigned*)(g_Vwh + (size_t)row0 * 128 + ncol)       = *(unsigned*)&p0;
                    *(unsigned*)(g_Vwh + (size_t)(row0 + 8) * 128 + ncol) = *(unsigned*)&p1;
                    *(unsigned*)(g_Vwl + (size_t)row0 * 128 + ncol) =
                        h2pk(v00 - __half2float(h00), v01 - __half2float(h01));
                    *(unsigned*)(g_Vwl + (size_t)(row0 + 8) * 128 + ncol) =
                        h2pk(v10 - __half2float(h10), v11 - __half2float(h11));
                }
            }
        }
    }
}

// ---------------- bias gather ----------------
__global__ void bias_build_kernel(const float* __restrict__ table,
                                  const int* __restrict__ ridx)
{
    int idx = blockIdx.x * 256 + threadIdx.x;
    if (idx < HEADS * NGT * NTOK) {
        int h  = idx / (NGT * NTOK);
        int ij = idx - h * (NGT * NTOK);
        g_bias[idx] = table[ridx[ij] * HEADS + h];
    }
}

// =====================================================================
// Window attention: 512 threads, 16 warps = (head, row-quarter).
// Fill = pure 16B copies (inputs already fp16). fp16 MMA pipeline.
// =====================================================================
#define WH_STR 136
#define WPLANE (64 * WH_STR)
#define WIN_SMEM (4 * WPLANE * 2)        // 69632 bytes

__global__ void __launch_bounds__(512)
win_attn_mma(const float* __restrict__ mask, float* __restrict__ out)
{
    extern __shared__ __half smh[];
    __half* sQ  = smh;
    __half* sK  = smh + WPLANE;
    __half* sVh = smh + 2 * WPLANE;
    __half* sVl = smh + 3 * WPLANE;

    const int w    = blockIdx.x;
    const int tid  = threadIdx.x;
    const int wid  = tid >> 5;
    const int h    = wid & 3;            // head
    const int qtr  = wid >> 2;           // row quarter (mf)
    const int lane = tid & 31;
    const int g4   = lane >> 2;
    const int t4   = lane & 3;

    // zero pad rows
    {
        uint4 z = make_uint4(0, 0, 0, 0);
        uint4* zq = (uint4*)(sQ + 49 * WH_STR);
        uint4* zk = (uint4*)(sK + 50 * WH_STR);
        uint4* zh = (uint4*)(sVh + 50 * WH_STR);
        uint4* zl = (uint4*)(sVl + 50 * WH_STR);
        for (int i = tid; i < 255; i += 512) zq[i] = z;
        for (int i = tid; i < 238; i += 512) { zk[i] = z; zh[i] = z; zl[i] = z; }
    }

    // fills: pure uint4 copies
    for (int idx = tid; idx < 49 * 16; idx += 512) {
        int r = idx >> 4, c = idx & 15;
        ((uint4*)(sQ + r * WH_STR))[c] =
            ((const uint4*)(g_Qh + (size_t)(w * NGT + r) * CDIM))[c];
    }
    for (int idx = tid; idx < 50 * 16; idx += 512) {
        int r = idx >> 4, c = idx & 15;
        size_t base = (size_t)(w * NTOK + r) * CDIM;
        ((uint4*)(sK  + r * WH_STR))[c] = ((const uint4*)(g_Kwh + base))[c];
        ((uint4*)(sVh + r * WH_STR))[c] = ((const uint4*)(g_Vwh + base))[c];
        ((uint4*)(sVl + r * WH_STR))[c] = ((const uint4*)(g_Vwl + base))[c];
    }
    __syncthreads();

    // ---- S = Q K^T : rows [16*qtr, 16*qtr+16) ----
    float sacc[7][4];
    #pragma unroll
    for (int nf = 0; nf < 7; nf++)
        #pragma unroll
        for (int c = 0; c < 4; c++) sacc[nf][c] = 0.0f;

    #pragma unroll
    for (int ks = 0; ks < 2; ks++) {
        const int kc = h * HD + ks * 16 + 2 * t4;
        unsigned a[4];
        const __half* ap = sQ + (16 * qtr + g4) * WH_STR + kc;
        a[0] = *(const unsigned*)(ap);
        a[1] = *(const unsigned*)(ap + 8 * WH_STR);
        a[2] = *(const unsigned*)(ap + 8);
        a[3] = *(const unsigned*)(ap + 8 * WH_STR + 8);
        #pragma unroll
        for (int nf = 0; nf < 7; nf++) {
            const __half* bp = sK + (8 * nf + g4) * WH_STR + kc;
            unsigned b0 = *(const unsigned*)(bp);
            unsigned b1 = *(const unsigned*)(bp + 8);
            mma_f16(sacc[nf], a, b0, b1);
        }
    }

    // ---- bias + mask + softmax ----
    const float* bptr = g_bias + h * (NGT * NTOK);
    const float* mptr = mask + (size_t)(w & 63) * (NGT * NTOK);
    const int i0 = 16 * qtr + g4;
    const int i1 = i0 + 8;
    float m0 = -1e30f, m1 = -1e30f;
    #pragma unroll
    for (int nf = 0; nf < 7; nf++) {
        const int j0 = 8 * nf + 2 * t4;
        const int j1 = j0 + 1;
        float s0 = (i0 < NGT && j0 < NTOK) ? sacc[nf][0] + bptr[i0 * 50 + j0] + mptr[i0 * 50 + j0] : -1e30f;
        float s1 = (i0 < NGT && j1 < NTOK) ? sacc[nf][1] + bptr[i0 * 50 + j1] + mptr[i0 * 50 + j1] : -1e30f;
        float s2 = (i1 < NGT && j0 < NTOK) ? sacc[nf][2] + bptr[i1 * 50 + j0] + mptr[i1 * 50 + j0] : -1e30f;
        float s3 = (i1 < NGT && j1 < NTOK) ? sacc[nf][3] + bptr[i1 * 50 + j1] + mptr[i1 * 50 + j1] : -1e30f;
        sacc[nf][0] = s0; sacc[nf][1] = s1;
        sacc[nf][2] = s2; sacc[nf][3] = s3;
        m0 = fmaxf(m0, fmaxf(s0, s1));
        m1 = fmaxf(m1, fmaxf(s2, s3));
    }
    m0 = fmaxf(m0, __shfl_xor_sync(0xffffffffu, m0, 1));
    m0 = fmaxf(m0, __shfl_xor_sync(0xffffffffu, m0, 2));
    m1 = fmaxf(m1, __shfl_xor_sync(0xffffffffu, m1, 1));
    m1 = fmaxf(m1, __shfl_xor_sync(0xffffffffu, m1, 2));
    float r0 = 0.0f, r1 = 0.0f;
    #pragma unroll
    for (int nf = 0; nf < 7; nf++) {
        float p0 = __expf(sacc[nf][0] - m0);
        float p1 = __expf(sacc[nf][1] - m0);
        float p2 = __expf(sacc[nf][2] - m1);
        float p3 = __expf(sacc[nf][3] - m1);
        sacc[nf][0] = p0; sacc[nf][1] = p1;
        sacc[nf][2] = p2; sacc[nf][3] = p3;
        r0 += p0 + p1;
        r1 += p2 + p3;
    }
    r0 += __shfl_xor_sync(0xffffffffu, r0, 1);
    r0 += __shfl_xor_sync(0xffffffffu, r0, 2);
    r1 += __shfl_xor_sync(0xffffffffu, r1, 1);
    r1 += __shfl_xor_sync(0xffffffffu, r1, 2);

    // ---- pack P into fp16 A-fragments ----
    unsigned pa[4][4];
    #pragma unroll
    for (int ks = 0; ks < 3; ks++) {
        pa[ks][0] = h2pk(sacc[2*ks][0],   sacc[2*ks][1]);
        pa[ks][1] = h2pk(sacc[2*ks][2],   sacc[2*ks][3]);
        pa[ks][2] = h2pk(sacc[2*ks+1][0], sacc[2*ks+1][1]);
        pa[ks][3] = h2pk(sacc[2*ks+1][2], sacc[2*ks+1][3]);
    }
    pa[3][0] = h2pk(sacc[6][0], sacc[6][1]);
    pa[3][1] = h2pk(sacc[6][2], sacc[6][3]);
    pa[3][2] = 0u;
    pa[3][3] = 0u;

    // ---- O = P V ----
    float oacc[4][4];
    #pragma unroll
    for (int nf = 0; nf < 4; nf++)
        #pragma unroll
        for (int c = 0; c < 4; c++) oacc[nf][c] = 0.0f;

    const int lr    = lane & 7;
    const int vbk   = ((lane >> 3) & 1) * 8;
    const int vnoff = ((lane >> 4) & 1) * 8;

    #pragma unroll
    for (int ks = 0; ks < 4; ks++) {
        unsigned bh[4][2], bl[4][2];
        #pragma unroll
        for (int p = 0; p < 2; p++) {
            const __half* vp = sVh + (ks * 16 + vbk + lr) * WH_STR + h * HD + 16 * p + vnoff;
            unsigned t[4];
            ldsm_x4_t(t, s2u(vp));
            bh[2*p][0] = t[0]; bh[2*p][1] = t[1];
            bh[2*p+1][0] = t[2]; bh[2*p+1][1] = t[3];
            ldsm_x4_t(t, s2u(vp + WPLANE));
            bl[2*p][0] = t[0]; bl[2*p][1] = t[1];
            bl[2*p+1][0] = t[2]; bl[2*p+1][1] = t[3];
        }
        #pragma unroll
        for (int nf = 0; nf < 4; nf++) {
            mma_f16(oacc[nf], pa[ks], bh[nf][0], bh[nf][1]);
            mma_f16(oacc[nf], pa[ks], bl[nf][0], bl[nf][1]);
        }
    }

    // ---- normalize + store ----
    const float inv0 = 1.0f / r0;
    const float inv1 = 1.0f / r1;
    #pragma unroll
    for (int nf = 0; nf < 4; nf++) {
        const int col = h * HD + 8 * nf + 2 * t4;
        if (i0 < NGT) {
            float2 v; v.x = oacc[nf][0] * inv0; v.y = oacc[nf][1] * inv0;
            *(float2*)(out + (size_t)(w * NGT + i0) * CDIM + col) = v;
        }
        if (i1 < NGT) {
            float2 v; v.x = oacc[nf][2] * inv1; v.y = oacc[nf][3] * inv1;
            *(float2*)(out + (size_t)(w * NGT + i1) * CDIM + col) = v;
        }
    }
}

// ---------------- global-token attention ----------------
__global__ void __launch_bounds__(512)
glob_attn_kernel(const float* __restrict__ xavg, const float* __restrict__ Wq,
                 const float* __restrict__ bq, float* __restrict__ out)
{
    const int b = blockIdx.x;
    const int h = blockIdx.y;
    const int tid  = threadIdx.x;
    const int warp = tid >> 5;
    const int lane = tid & 31;

    __shared__ float qa[32];
    __shared__ float logits[NTPAT];
    __shared__ float red[512];
    __shared__ float ored[16][33];

    if (tid < 32) {
        float acc = bq[h * HD + tid];
        const float* xr = xavg + (size_t)b * CDIM;
        for (int c = 0; c < CDIM; c++)
            acc += xr[c] * Wq[c * CDIM + h * HD + tid];
        qa[tid] = acc;
    }
    __syncthreads();

    const float* Kb = g_Kg + (size_t)b * NTPAT * CDIM + h * HD;
    const float  qv = qa[lane];
    for (int m0 = warp * 4; m0 < NTPAT; m0 += 64) {
        float p0 = qv * Kb[(size_t)(m0 + 0) * CDIM + lane];
        float p1 = qv * Kb[(size_t)(m0 + 1) * CDIM + lane];
        float p2 = qv * Kb[(size_t)(m0 + 2) * CDIM + lane];
        float p3 = qv * Kb[(size_t)(m0 + 3) * CDIM + lane];
        #pragma unroll
        for (int o = 16; o; o >>= 1) {
            p0 += __shfl_down_sync(0xffffffffu, p0, o);
            p1 += __shfl_down_sync(0xffffffffu, p1, o);
            p2 += __shfl_down_sync(0xffffffffu, p2, o);
            p3 += __shfl_down_sync(0xffffffffu, p3, o);
        }
        if (lane == 0) {
            logits[m0 + 0] = p0; logits[m0 + 1] = p1;
            logits[m0 + 2] = p2; logits[m0 + 3] = p3;
        }
    }
    __syncthreads();

    float mx = -1e30f;
    for (int m = tid; m < NTPAT; m += 512) mx = fmaxf(mx, logits[m]);
    red[tid] = mx; __syncthreads();
    for (int s = 256; s; s >>= 1) { if (tid < s) red[tid] = fmaxf(red[tid], red[tid + s]); __syncthreads(); }
    mx = red[0]; __syncthreads();

    float sum = 0.0f;
    for (int m = tid; m < NTPAT; m += 512) {
        float e = expf(logits[m] - mx);
        logits[m] = e;
        sum += e;
    }
    red[tid] = sum; __syncthreads();
    for (int s = 256; s; s >>= 1) { if (tid < s) red[tid] += red[tid + s]; __syncthreads(); }
    sum = red[0];
    __syncthreads();

    const float* Vb = g_Vg + (size_t)b * NTPAT * CDIM + h * HD;
    float acc = 0.0f;
    for (int m0 = warp * 4; m0 < NTPAT; m0 += 64) {
        float v0 = Vb[(size_t)(m0 + 0) * CDIM + lane];
        float v1 = Vb[(size_t)(m0 + 1) * CDIM + lane];
        float v2 = Vb[(size_t)(m0 + 2) * CDIM + lane];
        float v3 = Vb[(size_t)(m0 + 3) * CDIM + lane];
        acc += logits[m0] * v0 + logits[m0 + 1] * v1
             + logits[m0 + 2] * v2 + logits[m0 + 3] * v3;
    }
    ored[warp][lane] = acc;
    __syncthreads();
    if (tid < 32) {
        float a = 0.0f;
        #pragma unroll
        for (int p = 0; p < 16; p++) a += ored[p][tid];
        out[(size_t)b * CDIM + h * HD + tid] = a / sum;
    }
}

// ---------------- launch ----------------
extern "C" void kernel_launch(void* const* d_in, const int* in_sizes, int n_in,
                              void* d_out, int out_size)
{
    const float* x      = (const float*)d_in[0];
    const float* xtotal = (const float*)d_in[1];
    const float* xavg   = (const float*)d_in[2];
    const float* mask   = (const float*)d_in[3];
    const float* Wq     = (const float*)d_in[4];
    const float* bq     = (const float*)d_in[5];
    const float* Wkv    = (const float*)d_in[6];
    const float* bkv    = (const float*)d_in[7];
    const float* btab   = (const float*)d_in[8];
    const int*   ridx   = (const int*)d_in[9];

    float* out     = (float*)d_out;
    float* out_avg = out + (size_t)200704u * 128u;

    cudaFuncSetAttribute(bf16_gemm<0, 0>, cudaFuncAttributeMaxDynamicSharedMemorySize, GEMM_SMEM);
    cudaFuncSetAttribute(bf16_gemm<1, 1>, cudaFuncAttributeMaxDynamicSharedMemorySize, GEMM_SMEM);
    cudaFuncSetAttribute(bf16_gemm<0, 2>, cudaFuncAttributeMaxDynamicSharedMemorySize, GEMM_SMEM);
    cudaFuncSetAttribute(win_attn_mma, cudaFuncAttributeMaxDynamicSharedMemorySize, WIN_SMEM);

    bias_build_kernel<<<(HEADS * NGT * NTOK + 255) / 256, 256>>>(btab, ridx);

    bf16_gemm<0, 0><<<dim3(1, 1568), 256, GEMM_SMEM>>>(x, nullptr, Wq, bq, 128, WQ_SCALE);
    bf16_gemm<1, 1><<<dim3(2, 1600), 256, GEMM_SMEM>>>(x, xavg, Wkv, bkv, 256, 1.0f);
    bf16_gemm<0, 2><<<dim3(2, 1568), 256, GEMM_SMEM>>>(xtotal, nullptr, Wkv, bkv, 256, 1.0f);

    win_attn_mma<<<NWIN, 512, WIN_SMEM>>>(mask, out);
    glob_attn_kernel<<<dim3(BIMG, HEADS), 512>>>(xavg, Wq, bq, out_avg);
}

// round 10
// speedup vs baseline: 2.0438x; 1.1134x over previous
#include <cuda_runtime.h>
#include <cuda_bf16.h>
#include <cuda_fp16.h>

// ---------------- problem dims ----------------
#define NWIN   4096
#define NGT    49
#define NTOK   50
#define CDIM   128
#define HEADS  4
#define HD     32
#define BIMG   64
#define NTPAT  3136
#define WQ_SCALE 0.17677669529663687f   // 32^-0.5

// ---------------- device scratch ----------------
__device__ __half g_Qh [200704u * 128u];
__device__ __half g_Kwh[204800u * 128u];
__device__ __half g_Vwh[204800u * 128u];
__device__ __half g_Vwl[204800u * 128u];
__device__ float  g_Kg [200704u * 128u];
__device__ float  g_Vg [200704u * 128u];
__device__ float  g_bias[HEADS * NGT * NTOK];

// ---------------- helpers ----------------
__device__ __forceinline__ void mma_bf16(float* c, const unsigned* a,
                                         unsigned b0, unsigned b1)
{
    asm volatile("mma.sync.aligned.m16n8k16.row.col.f32.bf16.bf16.f32 "
                 "{%0,%1,%2,%3}, {%4,%5,%6,%7}, {%8,%9}, {%0,%1,%2,%3};"
                 : "+f"(c[0]), "+f"(c[1]), "+f"(c[2]), "+f"(c[3])
                 : "r"(a[0]), "r"(a[1]), "r"(a[2]), "r"(a[3]), "r"(b0), "r"(b1));
}
__device__ __forceinline__ void mma_f16(float* c, const unsigned* a,
                                        unsigned b0, unsigned b1)
{
    asm volatile("mma.sync.aligned.m16n8k16.row.col.f32.f16.f16.f32 "
                 "{%0,%1,%2,%3}, {%4,%5,%6,%7}, {%8,%9}, {%0,%1,%2,%3};"
                 : "+f"(c[0]), "+f"(c[1]), "+f"(c[2]), "+f"(c[3])
                 : "r"(a[0]), "r"(a[1]), "r"(a[2]), "r"(a[3]), "r"(b0), "r"(b1));
}
__device__ __forceinline__ void ldsm_x4(unsigned* r, unsigned addr) {
    asm volatile("ldmatrix.sync.aligned.m8n8.x4.shared.b16 {%0,%1,%2,%3}, [%4];"
                 : "=r"(r[0]), "=r"(r[1]), "=r"(r[2]), "=r"(r[3]) : "r"(addr));
}
__device__ __forceinline__ void ldsm_x4_t(unsigned* r, unsigned addr) {
    asm volatile("ldmatrix.sync.aligned.m8n8.x4.trans.shared.b16 {%0,%1,%2,%3}, [%4];"
                 : "=r"(r[0]), "=r"(r[1]), "=r"(r[2]), "=r"(r[3]) : "r"(addr));
}
__device__ __forceinline__ unsigned s2u(const void* p) {
    return (unsigned)__cvta_generic_to_shared(p);
}
__device__ __forceinline__ unsigned pk2(__nv_bfloat16 a, __nv_bfloat16 b) {
    __nv_bfloat162 t(a, b);
    return *reinterpret_cast<unsigned*>(&t);
}
__device__ __forceinline__ unsigned h2pk(float a, float b) {
    __half2 t = __floats2half2_rn(a, b);
    return *reinterpret_cast<unsigned*>(&t);
}

// =====================================================================
// Split-BF16 projection GEMM + ldmatrix + term-sliced MMA ordering.
// =====================================================================
#define SBB_STR 136
#define SAB_STR 40
#define SBB_PL  (128 * SBB_STR)
#define SAB_PL  (128 * SAB_STR)
#define GEMM_SMEM ((2 * SBB_PL + 4 * SAB_PL) * 2)   // 110592 bytes

template<int GATHER, int DST>
__global__ void __launch_bounds__(256, 2)
bf16_gemm(const float* __restrict__ A, const float* __restrict__ Aavg,
          const float* __restrict__ W, const float* __restrict__ bias,
          int N, float alpha)
{
    extern __shared__ __nv_bfloat16 sm[];
    __nv_bfloat16* sBh = sm;
    __nv_bfloat16* sBl = sm + SBB_PL;
    __nv_bfloat16* sA  = sm + 2 * SBB_PL;

    const int tid  = threadIdx.x;
    const int lane = tid & 31;
    const int warp = tid >> 5;
    const int wm   = warp >> 2;
    const int wn   = warp & 3;
    const int g4   = lane >> 2;
    const int t4   = lane & 3;
    const int nblk = blockIdx.x * 128;
    const int by   = blockIdx.y;

    const int lr    = lane & 7;
    const int lt8   = ((lane >> 3) & 1) * 8;
    const int lk8   = (lane >> 4) * 8;
    const int bnoff = ((lane >> 4) & 1) * 8;
    const int bk8   = ((lane >> 3) & 1) * 8;

    const int a_row  = tid >> 1;
    const int a_half = (tid & 1) * 16;
    const int m = by * 128 + a_row;
    const float* arow;
    if (GATHER) {
        int w  = m / NTOK;
        int rr = m - w * NTOK;
        arow = (rr < NGT) ? (A    + (size_t)(w * NGT + rr) * CDIM)
                          : (Aavg + (size_t)(w >> 6)       * CDIM);
    } else {
        arow = A + (size_t)m * CDIM;
    }

    // ---- B panel ----
    {
        const int nloc  = (warp & 3) * 32 + lane;
        const int kbase = (warp >> 2) * 64;
        const float* wp = W + nblk + nloc;
        #pragma unroll
        for (int kg = 0; kg < 16; kg++) {
            const int k = kbase + kg * 4;
            float v0 = wp[(size_t)(k + 0) * N];
            float v1 = wp[(size_t)(k + 1) * N];
            float v2 = wp[(size_t)(k + 2) * N];
            float v3 = wp[(size_t)(k + 3) * N];
            __nv_bfloat16 h0 = __float2bfloat16(v0);
            __nv_bfloat16 h1 = __float2bfloat16(v1);
            __nv_bfloat16 h2 = __float2bfloat16(v2);
            __nv_bfloat16 h3 = __float2bfloat16(v3);
            __nv_bfloat16 l0 = __float2bfloat16(v0 - __bfloat162float(h0));
            __nv_bfloat16 l1 = __float2bfloat16(v1 - __bfloat162float(h1));
            __nv_bfloat16 l2 = __float2bfloat16(v2 - __bfloat162float(h2));
            __nv_bfloat16 l3 = __float2bfloat16(v3 - __bfloat162float(h3));
            *(uint2*)(sBh + nloc * SBB_STR + k) = make_uint2(pk2(h0, h1), pk2(h2, h3));
            *(uint2*)(sBl + nloc * SBB_STR + k) = make_uint2(pk2(l0, l1), pk2(l2, l3));
        }
    }

    // ---- A prologue ----
    float4 areg[4];
    #pragma unroll
    for (int j = 0; j < 4; j++)
        areg[j] = *(const float4*)(arow + a_half + 4 * j);
    {
        __nv_bfloat16* dh = sA + a_row * SAB_STR + a_half;
        __nv_bfloat16* dl = dh + SAB_PL;
        #pragma unroll
        for (int j = 0; j < 4; j++) {
            __nv_bfloat16 h0 = __float2bfloat16(areg[j].x);
            __nv_bfloat16 h1 = __float2bfloat16(areg[j].y);
            __nv_bfloat16 h2 = __float2bfloat16(areg[j].z);
            __nv_bfloat16 h3 = __float2bfloat16(areg[j].w);
            __nv_bfloat16 l0 = __float2bfloat16(areg[j].x - __bfloat162float(h0));
            __nv_bfloat16 l1 = __float2bfloat16(areg[j].y - __bfloat162float(h1));
            __nv_bfloat16 l2 = __float2bfloat16(areg[j].z - __bfloat162float(h2));
            __nv_bfloat16 l3 = __float2bfloat16(areg[j].w - __bfloat162float(h3));
            *(uint2*)(dh + 4 * j) = make_uint2(pk2(h0, h1), pk2(h2, h3));
            *(uint2*)(dl + 4 * j) = make_uint2(pk2(l0, l1), pk2(l2, l3));
        }
    }
    __syncthreads();

    float acc[4][4][4];
    #pragma unroll
    for (int mf = 0; mf < 4; mf++)
        #pragma unroll
        for (int nf = 0; nf < 4; nf++)
            #pragma unroll
            for (int c = 0; c < 4; c++) acc[mf][nf][c] = 0.0f;

    const int a_m0 = wm * 64;
    const int b_n0 = wn * 32;

    for (int kt = 0; kt < 4; kt++) {
        if (kt < 3) {
            #pragma unroll
            for (int j = 0; j < 4; j++)
                areg[j] = *(const float4*)(arow + (kt + 1) * 32 + a_half + 4 * j);
        }
        const __nv_bfloat16* Ahp = sA + (kt & 1) * (2 * SAB_PL);

        #pragma unroll
        for (int st = 0; st < 2; st++) {
            const int kloc  = st * 16;
            const int kglob = kt * 32 + kloc;
            unsigned ah[4][4], al[4][4];
            #pragma unroll
            for (int mf = 0; mf < 4; mf++) {
                const __nv_bfloat16* pa_ = Ahp + (a_m0 + 16 * mf + lt8 + lr) * SAB_STR + kloc + lk8;
                ldsm_x4(ah[mf], s2u(pa_));
                ldsm_x4(al[mf], s2u(pa_ + SAB_PL));
            }
            unsigned bh[4][2], bl[4][2];
            #pragma unroll
            for (int p = 0; p < 2; p++) {
                const __nv_bfloat16* pb = sBh + (b_n0 + 16 * p + bnoff + lr) * SBB_STR + kglob + bk8;
                unsigned t[4];
                ldsm_x4(t, s2u(pb));
                bh[2*p][0] = t[0]; bh[2*p][1] = t[1];
                bh[2*p+1][0] = t[2]; bh[2*p+1][1] = t[3];
                ldsm_x4(t, s2u(pb + SBB_PL));
                bl[2*p][0] = t[0]; bl[2*p][1] = t[1];
                bl[2*p+1][0] = t[2]; bl[2*p+1][1] = t[3];
            }
            // term-sliced: each term sweeps all 16 accumulators before reuse
            // (per-accumulator addition order unchanged -> bit-identical)
            #pragma unroll
            for (int nf = 0; nf < 4; nf++)
                #pragma unroll
                for (int mf = 0; mf < 4; mf++)
                    mma_bf16(acc[mf][nf], ah[mf], bl[nf][0], bl[nf][1]);
            #pragma unroll
            for (int nf = 0; nf < 4; nf++)
                #pragma unroll
                for (int mf = 0; mf < 4; mf++)
                    mma_bf16(acc[mf][nf], al[mf], bh[nf][0], bh[nf][1]);
            #pragma unroll
            for (int nf = 0; nf < 4; nf++)
                #pragma unroll
                for (int mf = 0; mf < 4; mf++)
                    mma_bf16(acc[mf][nf], ah[mf], bh[nf][0], bh[nf][1]);
        }

        if (kt < 3) {
            __nv_bfloat16* dh = sA + ((kt + 1) & 1) * (2 * SAB_PL) + a_row * SAB_STR + a_half;
            __nv_bfloat16* dl = dh + SAB_PL;
            #pragma unroll
            for (int j = 0; j < 4; j++) {
                __nv_bfloat16 h0 = __float2bfloat16(areg[j].x);
                __nv_bfloat16 h1 = __float2bfloat16(areg[j].y);
                __nv_bfloat16 h2 = __float2bfloat16(areg[j].z);
                __nv_bfloat16 h3 = __float2bfloat16(areg[j].w);
                __nv_bfloat16 l0 = __float2bfloat16(areg[j].x - __bfloat162float(h0));
                __nv_bfloat16 l1 = __float2bfloat16(areg[j].y - __bfloat162float(h1));
                __nv_bfloat16 l2 = __float2bfloat16(areg[j].z - __bfloat162float(h2));
                __nv_bfloat16 l3 = __float2bfloat16(areg[j].w - __bfloat162float(h3));
                *(uint2*)(dh + 4 * j) = make_uint2(pk2(h0, h1), pk2(h2, h3));
                *(uint2*)(dl + 4 * j) = make_uint2(pk2(l0, l1), pk2(l2, l3));
            }
            __syncthreads();
        }
    }

    // ---- epilogue ----
    #pragma unroll
    for (int mf = 0; mf < 4; mf++) {
        int row0 = by * 128 + a_m0 + mf * 16 + g4;
        #pragma unroll
        for (int nf = 0; nf < 4; nf++) {
            int ncol = b_n0 + nf * 8 + 2 * t4;
            float bb0 = bias[nblk + ncol];
            float bb1 = bias[nblk + ncol + 1];
            float v00 = (acc[mf][nf][0] + bb0) * alpha;
            float v01 = (acc[mf][nf][1] + bb1) * alpha;
            float v10 = (acc[mf][nf][2] + bb0) * alpha;
            float v11 = (acc[mf][nf][3] + bb1) * alpha;
            if (DST == 2) {
                float* Cout = (blockIdx.x == 0) ? g_Kg : g_Vg;
                *(float2*)(Cout + (size_t)row0 * 128 + ncol)       = make_float2(v00, v01);
                *(float2*)(Cout + (size_t)(row0 + 8) * 128 + ncol) = make_float2(v10, v11);
            } else if (DST == 0) {
                *(unsigned*)(g_Qh + (size_t)row0 * 128 + ncol)       = h2pk(v00, v01);
                *(unsigned*)(g_Qh + (size_t)(row0 + 8) * 128 + ncol) = h2pk(v10, v11);
            } else {
                if (blockIdx.x == 0) {
                    *(unsigned*)(g_Kwh + (size_t)row0 * 128 + ncol)       = h2pk(v00, v01);
                    *(unsigned*)(g_Kwh + (size_t)(row0 + 8) * 128 + ncol) = h2pk(v10, v11);
                } else {
                    __half h00 = __float2half_rn(v00), h01 = __float2half_rn(v01);
                    __half h10 = __float2half_rn(v10), h11 = __float2half_rn(v11);
                    __half2 p0(h00, h01), p1(h10, h11);
                    *(unsigned*)(g_Vwh + (size_t)row0 * 128 + ncol)       = *(unsigned*)&p0;
                    *(unsigned*)(g_Vwh + (size_t)(row0 + 8) * 128 + ncol) = *(unsigned*)&p1;
                    *(unsigned*)(g_Vwl + (size_t)row0 * 128 + ncol) =
                        h2pk(v00 - __half2float(h00), v01 - __half2float(h01));
                    *(unsigned*)(g_Vwl + (size_t)(row0 + 8) * 128 + ncol) =
                        h2pk(v10 - __half2float(h10), v11 - __half2float(h11));
                }
            }
        }
    }
}

// ---------------- bias gather ----------------
__global__ void bias_build_kernel(const float* __restrict__ table,
                                  const int* __restrict__ ridx)
{
    int idx = blockIdx.x * 256 + threadIdx.x;
    if (idx < HEADS * NGT * NTOK) {
        int h  = idx / (NGT * NTOK);
        int ij = idx - h * (NGT * NTOK);
        g_bias[idx] = table[ridx[ij] * HEADS + h];
    }
}

// =====================================================================
// Window attention: 512 threads, 16 warps = (head, row-quarter).
// =====================================================================
#define WH_STR 136
#define WPLANE (64 * WH_STR)
#define WIN_SMEM (4 * WPLANE * 2)        // 69632 bytes

__global__ void __launch_bounds__(512)
win_attn_mma(const float* __restrict__ mask, float* __restrict__ out)
{
    extern __shared__ __half smh[];
    __half* sQ  = smh;
    __half* sK  = smh + WPLANE;
    __half* sVh = smh + 2 * WPLANE;
    __half* sVl = smh + 3 * WPLANE;

    const int w    = blockIdx.x;
    const int tid  = threadIdx.x;
    const int wid  = tid >> 5;
    const int h    = wid & 3;
    const int qtr  = wid >> 2;
    const int lane = tid & 31;
    const int g4   = lane >> 2;
    const int t4   = lane & 3;

    {
        uint4 z = make_uint4(0, 0, 0, 0);
        uint4* zq = (uint4*)(sQ + 49 * WH_STR);
        uint4* zk = (uint4*)(sK + 50 * WH_STR);
        uint4* zh = (uint4*)(sVh + 50 * WH_STR);
        uint4* zl = (uint4*)(sVl + 50 * WH_STR);
        for (int i = tid; i < 255; i += 512) zq[i] = z;
        for (int i = tid; i < 238; i += 512) { zk[i] = z; zh[i] = z; zl[i] = z; }
    }

    for (int idx = tid; idx < 49 * 16; idx += 512) {
        int r = idx >> 4, c = idx & 15;
        ((uint4*)(sQ + r * WH_STR))[c] =
            ((const uint4*)(g_Qh + (size_t)(w * NGT + r) * CDIM))[c];
    }
    for (int idx = tid; idx < 50 * 16; idx += 512) {
        int r = idx >> 4, c = idx & 15;
        size_t base = (size_t)(w * NTOK + r) * CDIM;
        ((uint4*)(sK  + r * WH_STR))[c] = ((const uint4*)(g_Kwh + base))[c];
        ((uint4*)(sVh + r * WH_STR))[c] = ((const uint4*)(g_Vwh + base))[c];
        ((uint4*)(sVl + r * WH_STR))[c] = ((const uint4*)(g_Vwl + base))[c];
    }
    __syncthreads();

    // ---- S = Q K^T ----
    float sacc[7][4];
    #pragma unroll
    for (int nf = 0; nf < 7; nf++)
        #pragma unroll
        for (int c = 0; c < 4; c++) sacc[nf][c] = 0.0f;

    #pragma unroll
    for (int ks = 0; ks < 2; ks++) {
        const int kc = h * HD + ks * 16 + 2 * t4;
        unsigned a[4];
        const __half* ap = sQ + (16 * qtr + g4) * WH_STR + kc;
        a[0] = *(const unsigned*)(ap);
        a[1] = *(const unsigned*)(ap + 8 * WH_STR);
        a[2] = *(const unsigned*)(ap + 8);
        a[3] = *(const unsigned*)(ap + 8 * WH_STR + 8);
        #pragma unroll
        for (int nf = 0; nf < 7; nf++) {
            const __half* bp = sK + (8 * nf + g4) * WH_STR + kc;
            unsigned b0 = *(const unsigned*)(bp);
            unsigned b1 = *(const unsigned*)(bp + 8);
            mma_f16(sacc[nf], a, b0, b1);
        }
    }

    // ---- bias + mask + softmax ----
    const float* bptr = g_bias + h * (NGT * NTOK);
    const float* mptr = mask + (size_t)(w & 63) * (NGT * NTOK);
    const int i0 = 16 * qtr + g4;
    const int i1 = i0 + 8;
    float m0 = -1e30f, m1 = -1e30f;
    #pragma unroll
    for (int nf = 0; nf < 7; nf++) {
        const int j0 = 8 * nf + 2 * t4;
        const int j1 = j0 + 1;
        float s0 = (i0 < NGT && j0 < NTOK) ? sacc[nf][0] + bptr[i0 * 50 + j0] + mptr[i0 * 50 + j0] : -1e30f;
        float s1 = (i0 < NGT && j1 < NTOK) ? sacc[nf][1] + bptr[i0 * 50 + j1] + mptr[i0 * 50 + j1] : -1e30f;
        float s2 = (i1 < NGT && j0 < NTOK) ? sacc[nf][2] + bptr[i1 * 50 + j0] + mptr[i1 * 50 + j0] : -1e30f;
        float s3 = (i1 < NGT && j1 < NTOK) ? sacc[nf][3] + bptr[i1 * 50 + j1] + mptr[i1 * 50 + j1] : -1e30f;
        sacc[nf][0] = s0; sacc[nf][1] = s1;
        sacc[nf][2] = s2; sacc[nf][3] = s3;
        m0 = fmaxf(m0, fmaxf(s0, s1));
        m1 = fmaxf(m1, fmaxf(s2, s3));
    }
    m0 = fmaxf(m0, __shfl_xor_sync(0xffffffffu, m0, 1));
    m0 = fmaxf(m0, __shfl_xor_sync(0xffffffffu, m0, 2));
    m1 = fmaxf(m1, __shfl_xor_sync(0xffffffffu, m1, 1));
    m1 = fmaxf(m1, __shfl_xor_sync(0xffffffffu, m1, 2));
    float r0 = 0.0f, r1 = 0.0f;
    #pragma unroll
    for (int nf = 0; nf < 7; nf++) {
        float p0 = __expf(sacc[nf][0] - m0);
        float p1 = __expf(sacc[nf][1] - m0);
        float p2 = __expf(sacc[nf][2] - m1);
        float p3 = __expf(sacc[nf][3] - m1);
        sacc[nf][0] = p0; sacc[nf][1] = p1;
        sacc[nf][2] = p2; sacc[nf][3] = p3;
        r0 += p0 + p1;
        r1 += p2 + p3;
    }
    r0 += __shfl_xor_sync(0xffffffffu, r0, 1);
    r0 += __shfl_xor_sync(0xffffffffu, r0, 2);
    r1 += __shfl_xor_sync(0xffffffffu, r1, 1);
    r1 += __shfl_xor_sync(0xffffffffu, r1, 2);

    // ---- pack P into fp16 A-fragments ----
    unsigned pa[4][4];
    #pragma unroll
    for (int ks = 0; ks < 3; ks++) {
        pa[ks][0] = h2pk(sacc[2*ks][0],   sacc[2*ks][1]);
        pa[ks][1] = h2pk(sacc[2*ks][2],   sacc[2*ks][3]);
        pa[ks][2] = h2pk(sacc[2*ks+1][0], sacc[2*ks+1][1]);
        pa[ks][3] = h2pk(sacc[2*ks+1][2], sacc[2*ks+1][3]);
    }
    pa[3][0] = h2pk(sacc[6][0], sacc[6][1]);
    pa[3][1] = h2pk(sacc[6][2], sacc[6][3]);
    pa[3][2] = 0u;
    pa[3][3] = 0u;

    // ---- O = P V ----
    float oacc[4][4];
    #pragma unroll
    for (int nf = 0; nf < 4; nf++)
        #pragma unroll
        for (int c = 0; c < 4; c++) oacc[nf][c] = 0.0f;

    const int lr    = lane & 7;
    const int vbk   = ((lane >> 3) & 1) * 8;
    const int vnoff = ((lane >> 4) & 1) * 8;

    #pragma unroll
    for (int ks = 0; ks < 4; ks++) {
        unsigned bh[4][2], bl[4][2];
        #pragma unroll
        for (int p = 0; p < 2; p++) {
            const __half* vp = sVh + (ks * 16 + vbk + lr) * WH_STR + h * HD + 16 * p + vnoff;
            unsigned t[4];
            ldsm_x4_t(t, s2u(vp));
            bh[2*p][0] = t[0]; bh[2*p][1] = t[1];
            bh[2*p+1][0] = t[2]; bh[2*p+1][1] = t[3];
            ldsm_x4_t(t, s2u(vp + WPLANE));
            bl[2*p][0] = t[0]; bl[2*p][1] = t[1];
            bl[2*p+1][0] = t[2]; bl[2*p+1][1] = t[3];
        }
        // term-sliced (per-accumulator order bh->bl preserved)
        #pragma unroll
        for (int nf = 0; nf < 4; nf++)
            mma_f16(oacc[nf], pa[ks], bh[nf][0], bh[nf][1]);
        #pragma unroll
        for (int nf = 0; nf < 4; nf++)
            mma_f16(oacc[nf], pa[ks], bl[nf][0], bl[nf][1]);
    }

    // ---- normalize + store ----
    const float inv0 = 1.0f / r0;
    const float inv1 = 1.0f / r1;
    #pragma unroll
    for (int nf = 0; nf < 4; nf++) {
        const int col = h * HD + 8 * nf + 2 * t4;
        if (i0 < NGT) {
            float2 v; v.x = oacc[nf][0] * inv0; v.y = oacc[nf][1] * inv0;
            *(float2*)(out + (size_t)(w * NGT + i0) * CDIM + col) = v;
        }
        if (i1 < NGT) {
            float2 v; v.x = oacc[nf][2] * inv1; v.y = oacc[nf][3] * inv1;
            *(float2*)(out + (size_t)(w * NGT + i1) * CDIM + col) = v;
        }
    }
}

// ---------------- global-token attention ----------------
__global__ void __launch_bounds__(512)
glob_attn_kernel(const float* __restrict__ xavg, const float* __restrict__ Wq,
                 const float* __restrict__ bq, float* __restrict__ out)
{
    const int b = blockIdx.x;
    const int h = blockIdx.y;
    const int tid  = threadIdx.x;
    const int warp = tid >> 5;
    const int lane = tid & 31;

    __shared__ float qa[32];
    __shared__ float logits[NTPAT];
    __shared__ float red[512];
    __shared__ float ored[16][33];

    if (tid < 32) {
        float acc = bq[h * HD + tid];
        const float* xr = xavg + (size_t)b * CDIM;
        for (int c = 0; c < CDIM; c++)
            acc += xr[c] * Wq[c * CDIM + h * HD + tid];
        qa[tid] = acc;
    }
    __syncthreads();

    const float* Kb = g_Kg + (size_t)b * NTPAT * CDIM + h * HD;
    const float  qv = qa[lane];
    for (int m0 = warp * 4; m0 < NTPAT; m0 += 64) {
        float p0 = qv * Kb[(size_t)(m0 + 0) * CDIM + lane];
        float p1 = qv * Kb[(size_t)(m0 + 1) * CDIM + lane];
        float p2 = qv * Kb[(size_t)(m0 + 2) * CDIM + lane];
        float p3 = qv * Kb[(size_t)(m0 + 3) * CDIM + lane];
        #pragma unroll
        for (int o = 16; o; o >>= 1) {
            p0 += __shfl_down_sync(0xffffffffu, p0, o);
            p1 += __shfl_down_sync(0xffffffffu, p1, o);
            p2 += __shfl_down_sync(0xffffffffu, p2, o);
            p3 += __shfl_down_sync(0xffffffffu, p3, o);
        }
        if (lane == 0) {
            logits[m0 + 0] = p0; logits[m0 + 1] = p1;
            logits[m0 + 2] = p2; logits[m0 + 3] = p3;
        }
    }
    __syncthreads();

    float mx = -1e30f;
    for (int m = tid; m < NTPAT; m += 512) mx = fmaxf(mx, logits[m]);
    red[tid] = mx; __syncthreads();
    for (int s = 256; s; s >>= 1) { if (tid < s) red[tid] = fmaxf(red[tid], red[tid + s]); __syncthreads(); }
    mx = red[0]; __syncthreads();

    float sum = 0.0f;
    for (int m = tid; m < NTPAT; m += 512) {
        float e = expf(logits[m] - mx);
        logits[m] = e;
        sum += e;
    }
    red[tid] = sum; __syncthreads();
    for (int s = 256; s; s >>= 1) { if (tid < s) red[tid] += red[tid + s]; __syncthreads(); }
    sum = red[0];
    __syncthreads();

    const float* Vb = g_Vg + (size_t)b * NTPAT * CDIM + h * HD;
    float acc = 0.0f;
    for (int m0 = warp * 4; m0 < NTPAT; m0 += 64) {
        float v0 = Vb[(size_t)(m0 + 0) * CDIM + lane];
        float v1 = Vb[(size_t)(m0 + 1) * CDIM + lane];
        float v2 = Vb[(size_t)(m0 + 2) * CDIM + lane];
        float v3 = Vb[(size_t)(m0 + 3) * CDIM + lane];
        acc += logits[m0] * v0 + logits[m0 + 1] * v1
             + logits[m0 + 2] * v2 + logits[m0 + 3] * v3;
    }
    ored[warp][lane] = acc;
    __syncthreads();
    if (tid < 32) {
        float a = 0.0f;
        #pragma unroll
        for (int p = 0; p < 16; p++) a += ored[p][tid];
        out[(size_t)b * CDIM + h * HD + tid] = a / sum;
    }
}

// ---------------- launch ----------------
extern "C" void kernel_launch(void* const* d_in, const int* in_sizes, int n_in,
                              void* d_out, int out_size)
{
    const float* x      = (const float*)d_in[0];
    const float* xtotal = (const float*)d_in[1];
    const float* xavg   = (const float*)d_in[2];
    const float* mask   = (const float*)d_in[3];
    const float* Wq     = (const float*)d_in[4];
    const float* bq     = (const float*)d_in[5];
    const float* Wkv    = (const float*)d_in[6];
    const float* bkv    = (const float*)d_in[7];
    const float* btab   = (const float*)d_in[8];
    const int*   ridx   = (const int*)d_in[9];

    float* out     = (float*)d_out;
    float* out_avg = out + (size_t)200704u * 128u;

    static cudaStream_t s2 = nullptr;
    static cudaEvent_t evF = nullptr, evJ = nullptr;
    if (s2 == nullptr) {
        cudaStreamCreateWithFlags(&s2, cudaStreamNonBlocking);
        cudaEventCreateWithFlags(&evF, cudaEventDisableTiming);
        cudaEventCreateWithFlags(&evJ, cudaEventDisableTiming);
        cudaFuncSetAttribute(bf16_gemm<0, 0>, cudaFuncAttributeMaxDynamicSharedMemorySize, GEMM_SMEM);
        cudaFuncSetAttribute(bf16_gemm<1, 1>, cudaFuncAttributeMaxDynamicSharedMemorySize, GEMM_SMEM);
        cudaFuncSetAttribute(bf16_gemm<0, 2>, cudaFuncAttributeMaxDynamicSharedMemorySize, GEMM_SMEM);
        cudaFuncSetAttribute(win_attn_mma, cudaFuncAttributeMaxDynamicSharedMemorySize, WIN_SMEM);
    }

    // fork: global-path chain (gemm<0,2> -> glob_attn) runs on s2
    cudaEventRecord(evF, 0);
    cudaStreamWaitEvent(s2, evF, 0);

    bf16_gemm<0, 2><<<dim3(2, 1568), 256, GEMM_SMEM, s2>>>(xtotal, nullptr, Wkv, bkv, 256, 1.0f);
    glob_attn_kernel<<<dim3(BIMG, HEADS), 512, 0, s2>>>(xavg, Wq, bq, out_avg);
    cudaEventRecord(evJ, s2);

    // window-path chain on the default stream
    bias_build_kernel<<<(HEADS * NGT * NTOK + 255) / 256, 256>>>(btab, ridx);
    bf16_gemm<0, 0><<<dim3(1, 1568), 256, GEMM_SMEM>>>(x, nullptr, Wq, bq, 128, WQ_SCALE);
    bf16_gemm<1, 1><<<dim3(2, 1600), 256, GEMM_SMEM>>>(x, xavg, Wkv, bkv, 256, 1.0f);
    win_attn_mma<<<NWIN, 512, WIN_SMEM>>>(mask, out);

    // join
    cudaStreamWaitEvent(0, evJ, 0);
}